// round 6
// baseline (speedup 1.0000x reference)
#include <cuda_runtime.h>
#include <cuda_bf16.h>
#include <math.h>

// ---------------------------------------------------------------------------
// Scratch (allocation-free device globals)
// ---------------------------------------------------------------------------
__device__ float g_bufA[64 * 128 * 128];                  // pre-norm L1 acts
__device__ __align__(16) float g_wt1[16384 * 49];         // [k][pix]
__device__ __align__(16) float g_wt2[4096 * 25];
__device__ __align__(16) float g_wt3[4096 * 25];
__device__ __align__(16) float g_wt4[1024 * 9];
__device__ __align__(16) float g_wt5[1024 * 9];
__device__ __align__(16) float g_wt6[256 * 9];
__device__ float4 g_fcwt[64 * 1024];                      // [kk][o]
__device__ __align__(16) float g_feat[64 * 256];          // L6 output features

// ===========================================================================
// Weight transposes (coalesced both sides)
// ===========================================================================
__global__ __launch_bounds__(256) void transpose_lc(
    const float* __restrict__ w1, const float* __restrict__ w2,
    const float* __restrict__ w3, const float* __restrict__ w4,
    const float* __restrict__ w5, const float* __restrict__ w6,
    float* __restrict__ t1, float* __restrict__ t2, float* __restrict__ t3,
    float* __restrict__ t4, float* __restrict__ t5, float* __restrict__ t6) {
    __shared__ float s[32 * 49];
    int tile = blockIdx.x;
    const float* in; float* out; int N, K;
    if      (tile < 512) {             in = w1; out = t1; N = 16384; K = 49; }
    else if (tile < 640) { tile -= 512; in = w2; out = t2; N = 4096;  K = 25; }
    else if (tile < 768) { tile -= 640; in = w3; out = t3; N = 4096;  K = 25; }
    else if (tile < 800) { tile -= 768; in = w4; out = t4; N = 1024;  K = 9;  }
    else if (tile < 832) { tile -= 800; in = w5; out = t5; N = 1024;  K = 9;  }
    else                 { tile -= 832; in = w6; out = t6; N = 256;   K = 9;  }
    const int p0  = tile * 32;
    const int tot = 32 * K;
    const int tid = threadIdx.x;
    for (int idx = tid; idx < tot; idx += 256) s[idx] = in[(size_t)p0 * K + idx];
    __syncthreads();
    for (int idx = tid; idx < tot; idx += 256) {
        int k = idx >> 5, pl = idx & 31;
        out[(size_t)k * N + p0 + pl] = s[pl * K + k];
    }
}

__global__ __launch_bounds__(256) void transpose_fc(const float4* __restrict__ in,
                                                    float4* __restrict__ out) {
    __shared__ float4 s[32 * 65];
    const int o0  = blockIdx.x * 32;
    const int tid = threadIdx.x;
    for (int idx = tid; idx < 32 * 64; idx += 256) {
        int ol = idx >> 6, kk = idx & 63;
        s[ol * 65 + kk] = in[(size_t)(o0 + ol) * 64 + kk];
    }
    __syncthreads();
    for (int idx = tid; idx < 32 * 64; idx += 256) {
        int kk = idx >> 5, ol = idx & 31;
        out[(size_t)kk * 1024 + o0 + ol] = s[ol * 65 + kk];
    }
}

// ===========================================================================
// Kernel A: L1 LC + ReLU (k-major weights), weights reused across 8 images.
// ===========================================================================
template <int RPB, int BCH>
__global__ __launch_bounds__(512) void lc1_kernel(const float* __restrict__ in,
                                                  const float* __restrict__ wt,
                                                  const float* __restrict__ bias,
                                                  float* __restrict__ act) {
    constexpr int H = 128, W = 128, K = 7, PAD = 3, KK = 49, N = H * W;
    constexpr int IW = W + 2 * PAD;
    constexpr int IR = RPB + 2 * PAD;
    constexpr int NT = RPB * W;

    __shared__ float sin[IR * IW];

    const int r0  = blockIdx.x * RPB;
    const int b0  = blockIdx.y * BCH;
    const int tid = threadIdx.x;
    const int li  = tid / W;
    const int lj  = tid % W;
    const int pix = (r0 + li) * W + lj;

    float wr[KK];
#pragma unroll
    for (int t = 0; t < KK; t++) wr[t] = wt[(size_t)t * N + pix];
    const float bb = bias[pix];

    for (int bi = 0; bi < BCH; bi++) {
        const int b = b0 + bi;
        const float* inb = in + (size_t)b * N;
        __syncthreads();
        for (int idx = tid; idx < IR * IW; idx += NT) {
            int r = idx / IW, c = idx % IW;
            int gi = r0 - PAD + r, gj = c - PAD;
            float v = 0.f;
            if (gi >= 0 && gi < H && gj >= 0 && gj < W) v = inb[gi * W + gj];
            sin[idx] = v;
        }
        __syncthreads();

        float sum = bb;
#pragma unroll
        for (int kh = 0; kh < K; kh++)
#pragma unroll
            for (int kw = 0; kw < K; kw++)
                sum = fmaf(wr[kh * K + kw], sin[(li + kh) * IW + (lj + kw)], sum);

        act[(size_t)b * N + pix] = fmaxf(sum, 0.f);
    }
}

// ===========================================================================
// Kernel B: fused L1-norm..L6.  One block per image, 1024 threads.
// ===========================================================================
#define NTB 1024

__device__ __forceinline__ void block_sum2(float& s, float& q, float* red) {
    __syncthreads();
#pragma unroll
    for (int o = 16; o > 0; o >>= 1) {
        s += __shfl_down_sync(0xffffffffu, s, o);
        q += __shfl_down_sync(0xffffffffu, q, o);
    }
    const int wid = threadIdx.x >> 5, lane = threadIdx.x & 31;
    if (lane == 0) { red[wid] = s; red[32 + wid] = q; }
    __syncthreads();
    if (wid == 0) {
        s = red[lane]; q = red[32 + lane];
#pragma unroll
        for (int o = 16; o > 0; o >>= 1) {
            s += __shfl_down_sync(0xffffffffu, s, o);
            q += __shfl_down_sync(0xffffffffu, q, o);
        }
        if (lane == 0) { red[0] = s; red[32] = q; }
    }
    __syncthreads();
    s = red[0]; q = red[32];
}

// L2/L3: H=64, K=5, 4 consecutive pixels per thread via float4 weights.
__device__ __forceinline__ void lc64_v4(const float4* __restrict__ wt4,
                                        const float4* __restrict__ b4,
                                        const float* s_in, float* s_act,
                                        float& mean, float& rstd, float* red) {
    constexpr int PWIDTH = 68;
    const int tid = threadIdx.x;
    const int p0 = tid * 4;
    const int i = p0 >> 6, j = p0 & 63;          // 4 pixels, same row
    const float* sp0 = s_in + i * PWIDTH + j;
    float4 acc = b4[tid];
#pragma unroll
    for (int kh = 0; kh < 5; kh++)
#pragma unroll
        for (int kw = 0; kw < 5; kw++) {
            float4 w = wt4[(size_t)(kh * 5 + kw) * 1024 + tid];
            const float* sp = sp0 + kh * PWIDTH + kw;
            acc.x = fmaf(w.x, sp[0], acc.x);
            acc.y = fmaf(w.y, sp[1], acc.y);
            acc.z = fmaf(w.z, sp[2], acc.z);
            acc.w = fmaf(w.w, sp[3], acc.w);
        }
    float4 v = make_float4(fmaxf(acc.x, 0.f), fmaxf(acc.y, 0.f),
                           fmaxf(acc.z, 0.f), fmaxf(acc.w, 0.f));
    ((float4*)s_act)[tid] = v;
    float s = v.x + v.y + v.z + v.w;
    float q = v.x * v.x + v.y * v.y + v.z * v.z + v.w * v.w;
    block_sum2(s, q, red);
    mean = s * (1.0f / 4096.0f);
    rstd = rsqrtf(q * (1.0f / 4096.0f) - mean * mean + 1e-5f);
}

// L4/L5/L6: small layers, scalar, one pixel per thread (tid < N).
template <int H, int PWIDTH>
__device__ __forceinline__ void lc_small(const float* __restrict__ wt,
                                         const float* __restrict__ bias,
                                         const float* s_in, float* s_act,
                                         float& mean, float& rstd, float* red) {
    constexpr int N = H * H;
    const int tid = threadIdx.x;
    float s = 0.f, q = 0.f;
    if (tid < N) {
        const int i = tid / H, j = tid % H;
        const float* sp0 = s_in + i * PWIDTH + j;
        float acc = bias[tid];
#pragma unroll
        for (int kh = 0; kh < 3; kh++)
#pragma unroll
            for (int kw = 0; kw < 3; kw++)
                acc = fmaf(wt[(size_t)(kh * 3 + kw) * N + tid],
                           sp0[kh * PWIDTH + kw], acc);
        float v = fmaxf(acc, 0.f);
        s_act[tid] = v;
        s = v; q = v * v;
    }
    block_sum2(s, q, red);
    mean = s * (1.0f / N);
    rstd = rsqrtf(q * (1.0f / N) - mean * mean + 1e-5f);
}

__global__ __launch_bounds__(NTB) void fused_kernel(
    const float* __restrict__ bufA,
    const float* __restrict__ g1, const float* __restrict__ be1,
    const float4* __restrict__ wt2, const float4* __restrict__ b2,
    const float4* __restrict__ g2, const float4* __restrict__ be2,
    const float4* __restrict__ wt3, const float4* __restrict__ b3,
    const float* __restrict__ g3, const float* __restrict__ be3,
    const float* __restrict__ wt4, const float* __restrict__ b4,
    const float* __restrict__ g4, const float* __restrict__ be4,
    const float* __restrict__ wt5, const float* __restrict__ b5,
    const float* __restrict__ g5, const float* __restrict__ be5,
    const float* __restrict__ wt6, const float* __restrict__ b6,
    const float* __restrict__ g6, const float* __restrict__ be6,
    float* __restrict__ feat) {

    __shared__ __align__(16) float s_pad64[68 * 68];   // L2/L3 input, origin (2,2)
    __shared__ __align__(16) float s_pad32[34 * 34];   // L4/L5 input, origin (1,1)
    __shared__ __align__(16) float s_pad16[18 * 18];   // L6 input,    origin (1,1)
    __shared__ __align__(16) float s_act[64 * 64];
    __shared__ float s_red[64];

    const int b   = blockIdx.x;
    const int tid = threadIdx.x;
    const float* ab = bufA + (size_t)b * 128 * 128;

    // zero all halos once (interiors are fully overwritten each use)
    for (int p = tid; p < 68 * 68; p += NTB) s_pad64[p] = 0.f;
    for (int p = tid; p < 34 * 34; p += NTB) s_pad32[p] = 0.f;
    for (int p = tid; p < 18 * 18; p += NTB) s_pad16[p] = 0.f;

    // ---------------- L1 stats + norm + pool -> s_pad64 --------------------
    {
        float s = 0.f, q = 0.f;
        const float4* a4 = (const float4*)ab;
        for (int p = tid; p < 128 * 128 / 4; p += NTB) {
            float4 v = a4[p];
            s += v.x + v.y + v.z + v.w;
            q += v.x * v.x + v.y * v.y + v.z * v.z + v.w * v.w;
        }
        block_sum2(s, q, s_red);   // also covers the zeroing above
        const float mean = s * (1.0f / 16384.0f);
        const float rstd = rsqrtf(q * (1.0f / 16384.0f) - mean * mean + 1e-5f);

        for (int p = tid; p < 64 * 64; p += NTB) {
            const int oi = p >> 6, oj = p & 63;
            float m = -INFINITY;
#pragma unroll
            for (int di = 0; di < 2; di++)
#pragma unroll
                for (int dj = 0; dj < 2; dj++) {
                    const int idx = (2 * oi + di) * 128 + (2 * oj + dj);
                    float v = (ab[idx] - mean) * rstd * g1[idx] + be1[idx];
                    m = fmaxf(m, v);
                }
            s_pad64[(oi + 2) * 68 + (oj + 2)] = m;
        }
        __syncthreads();
    }

    float mean, rstd;

    // ---------------- L2 ----------------------------------------------------
    lc64_v4(wt2, b2, s_pad64, s_act, mean, rstd, s_red);
    {
        const int p0 = tid * 4;
        const int i = p0 >> 6, j = p0 & 63;
        float4 v = ((const float4*)s_act)[tid];
        float4 gg = g2[tid], bb = be2[tid];
        float* dst = s_pad64 + (i + 2) * 68 + (j + 2);
        dst[0] = (v.x - mean) * rstd * gg.x + bb.x;
        dst[1] = (v.y - mean) * rstd * gg.y + bb.y;
        dst[2] = (v.z - mean) * rstd * gg.z + bb.z;
        dst[3] = (v.w - mean) * rstd * gg.w + bb.w;
        __syncthreads();
    }

    // ---------------- L3 + pool -> s_pad32 ----------------------------------
    lc64_v4(wt3, b3, s_pad64, s_act, mean, rstd, s_red);
    {
        if (tid < 32 * 32) {
            const int oi = tid >> 5, oj = tid & 31;
            float m = -INFINITY;
#pragma unroll
            for (int di = 0; di < 2; di++)
#pragma unroll
                for (int dj = 0; dj < 2; dj++) {
                    const int idx = (2 * oi + di) * 64 + (2 * oj + dj);
                    float v = (s_act[idx] - mean) * rstd * g3[idx] + be3[idx];
                    m = fmaxf(m, v);
                }
            s_pad32[(oi + 1) * 34 + (oj + 1)] = m;
        }
        __syncthreads();
    }

    // ---------------- L4 ----------------------------------------------------
    lc_small<32, 34>(wt4, b4, s_pad32, s_act, mean, rstd, s_red);
    {
        if (tid < 32 * 32) {
            const int i = tid >> 5, j = tid & 31;
            float v = (s_act[tid] - mean) * rstd * g4[tid] + be4[tid];
            s_pad32[(i + 1) * 34 + (j + 1)] = v;
        }
        __syncthreads();
    }

    // ---------------- L5 + pool -> s_pad16 ----------------------------------
    lc_small<32, 34>(wt5, b5, s_pad32, s_act, mean, rstd, s_red);
    {
        if (tid < 16 * 16) {
            const int oi = tid >> 4, oj = tid & 15;
            float m = -INFINITY;
#pragma unroll
            for (int di = 0; di < 2; di++)
#pragma unroll
                for (int dj = 0; dj < 2; dj++) {
                    const int idx = (2 * oi + di) * 32 + (2 * oj + dj);
                    float v = (s_act[idx] - mean) * rstd * g5[idx] + be5[idx];
                    m = fmaxf(m, v);
                }
            s_pad16[(oi + 1) * 18 + (oj + 1)] = m;
        }
        __syncthreads();
    }

    // ---------------- L6 -> features to gmem --------------------------------
    lc_small<16, 18>(wt6, b6, s_pad16, s_act, mean, rstd, s_red);
    if (tid < 256) {
        float v = (s_act[tid] - mean) * rstd * g6[tid] + be6[tid];
        feat[(size_t)b * 256 + tid] = v;
    }
}

// ===========================================================================
// Kernel C: FC 256->1024 + softmax.  32 blocks x 256 thr, 2 images per block.
// ===========================================================================
__global__ __launch_bounds__(256) void fc_softmax_kernel(const float* __restrict__ feat,
                                                         const float4* __restrict__ fcwt,
                                                         const float* __restrict__ fcb,
                                                         float* __restrict__ out) {
    __shared__ float4 sx[2][64];
    __shared__ float sred[16];
    const int tid = threadIdx.x;
    const int b0 = blockIdx.x * 2;

    if (tid < 128) {
        int bi = tid >> 6, kk = tid & 63;
        sx[bi][kk] = ((const float4*)feat)[(size_t)(b0 + bi) * 64 + kk];
    }
    __syncthreads();

    float l[4][2];
#pragma unroll
    for (int r = 0; r < 4; r++) {
        const int o = tid + r * 256;
        const float bb = fcb[o];
        float a0 = bb, a1 = bb;
#pragma unroll 4
        for (int kk = 0; kk < 64; kk++) {
            float4 w = fcwt[(size_t)kk * 1024 + o];
            float4 x0 = sx[0][kk], x1 = sx[1][kk];
            a0 = fmaf(w.x, x0.x, a0); a0 = fmaf(w.y, x0.y, a0);
            a0 = fmaf(w.z, x0.z, a0); a0 = fmaf(w.w, x0.w, a0);
            a1 = fmaf(w.x, x1.x, a1); a1 = fmaf(w.y, x1.y, a1);
            a1 = fmaf(w.z, x1.z, a1); a1 = fmaf(w.w, x1.w, a1);
        }
        l[r][0] = a0; l[r][1] = a1;
    }

    const int wid = tid >> 5, lane = tid & 31;

    // ---- max ----
    float m[2];
#pragma unroll
    for (int bi = 0; bi < 2; bi++)
        m[bi] = fmaxf(fmaxf(l[0][bi], l[1][bi]), fmaxf(l[2][bi], l[3][bi]));
#pragma unroll
    for (int o = 16; o > 0; o >>= 1)
#pragma unroll
        for (int bi = 0; bi < 2; bi++)
            m[bi] = fmaxf(m[bi], __shfl_xor_sync(0xffffffffu, m[bi], o));
    if (lane == 0) { sred[wid * 2] = m[0]; sred[wid * 2 + 1] = m[1]; }
    __syncthreads();
    float M[2];
#pragma unroll
    for (int bi = 0; bi < 2; bi++) {
        float mm = sred[bi];
#pragma unroll
        for (int w = 1; w < 8; w++) mm = fmaxf(mm, sred[w * 2 + bi]);
        M[bi] = mm;
    }
    __syncthreads();

    // ---- sum of exp ----
    float s[2] = {0.f, 0.f};
#pragma unroll
    for (int r = 0; r < 4; r++)
#pragma unroll
        for (int bi = 0; bi < 2; bi++) {
            l[r][bi] = __expf(l[r][bi] - M[bi]);
            s[bi] += l[r][bi];
        }
#pragma unroll
    for (int o = 16; o > 0; o >>= 1)
#pragma unroll
        for (int bi = 0; bi < 2; bi++)
            s[bi] += __shfl_xor_sync(0xffffffffu, s[bi], o);
    if (lane == 0) { sred[wid * 2] = s[0]; sred[wid * 2 + 1] = s[1]; }
    __syncthreads();
    float R[2];
#pragma unroll
    for (int bi = 0; bi < 2; bi++) {
        float ss = 0.f;
#pragma unroll
        for (int w = 0; w < 8; w++) ss += sred[w * 2 + bi];
        R[bi] = 1.0f / ss;
    }

#pragma unroll
    for (int r = 0; r < 4; r++) {
        const int o = tid + r * 256;
#pragma unroll
        for (int bi = 0; bi < 2; bi++)
            out[(size_t)(b0 + bi) * 1024 + o] = l[r][bi] * R[bi];
    }
}

// ===========================================================================
// Launch
// ===========================================================================
extern "C" void kernel_launch(void* const* d_in, const int* in_sizes, int n_in,
                              void* d_out, int out_size) {
    (void)in_sizes; (void)n_in; (void)out_size;

    const float* x   = (const float*)d_in[0];
    const float* w1  = (const float*)d_in[1];
    const float* b1  = (const float*)d_in[2];
    const float* g1  = (const float*)d_in[3];
    const float* be1 = (const float*)d_in[4];
    const float* w2  = (const float*)d_in[5];
    const float* b2  = (const float*)d_in[6];
    const float* g2  = (const float*)d_in[7];
    const float* be2 = (const float*)d_in[8];
    const float* w3  = (const float*)d_in[9];
    const float* b3  = (const float*)d_in[10];
    const float* g3  = (const float*)d_in[11];
    const float* be3 = (const float*)d_in[12];
    const float* w4  = (const float*)d_in[13];
    const float* b4  = (const float*)d_in[14];
    const float* g4  = (const float*)d_in[15];
    const float* be4 = (const float*)d_in[16];
    const float* w5  = (const float*)d_in[17];
    const float* b5  = (const float*)d_in[18];
    const float* g5  = (const float*)d_in[19];
    const float* be5 = (const float*)d_in[20];
    const float* w6  = (const float*)d_in[21];
    const float* b6  = (const float*)d_in[22];
    const float* g6  = (const float*)d_in[23];
    const float* be6 = (const float*)d_in[24];
    const float* fcw = (const float*)d_in[25];
    const float* fcb = (const float*)d_in[26];
    float* out = (float*)d_out;

    float *A, *t1, *t2, *t3, *t4, *t5, *t6, *feat;
    float4* fct;
    cudaGetSymbolAddress((void**)&A,    g_bufA);
    cudaGetSymbolAddress((void**)&t1,   g_wt1);
    cudaGetSymbolAddress((void**)&t2,   g_wt2);
    cudaGetSymbolAddress((void**)&t3,   g_wt3);
    cudaGetSymbolAddress((void**)&t4,   g_wt4);
    cudaGetSymbolAddress((void**)&t5,   g_wt5);
    cudaGetSymbolAddress((void**)&t6,   g_wt6);
    cudaGetSymbolAddress((void**)&fct,  g_fcwt);
    cudaGetSymbolAddress((void**)&feat, g_feat);

    transpose_lc<<<840, 256>>>(w1, w2, w3, w4, w5, w6, t1, t2, t3, t4, t5, t6);
    transpose_fc<<<32, 256>>>((const float4*)fcw, fct);

    lc1_kernel<4, 8><<<dim3(32, 8), 512>>>(x, t1, b1, A);

    fused_kernel<<<64, NTB>>>(A,
        g1, be1,
        (const float4*)t2, (const float4*)b2, (const float4*)g2, (const float4*)be2,
        (const float4*)t3, (const float4*)b3, g3, be3,
        t4, b4, g4, be4, t5, b5, g5, be5, t6, b6, g6, be6,
        feat);

    fc_softmax_kernel<<<32, 256>>>(feat, fct, fcb, out);
}

// round 8
// speedup vs baseline: 1.1005x; 1.1005x over previous
#include <cuda_runtime.h>
#include <cuda_bf16.h>
#include <math.h>

// ---------------------------------------------------------------------------
// Scratch (allocation-free device globals)
// ---------------------------------------------------------------------------
__device__ float g_bufA[64 * 128 * 128];                  // pre-norm L1 acts
__device__ __align__(16) float g_wt1[16384 * 49];         // [k][pix]
__device__ __align__(16) float g_wt2[4096 * 25];
__device__ __align__(16) float g_wt3[4096 * 25];
__device__ __align__(16) float g_wt4[1024 * 9];
__device__ __align__(16) float g_wt5[1024 * 9];
__device__ __align__(16) float g_wt6[256 * 9];
__device__ __align__(16) float g_featT[256 * 64];         // [k][img]
__device__ __align__(16) float g_logits[64 * 1024];
__device__ float g_accS[64];                              // L1 LN sums
__device__ float g_accQ[64];

// ===========================================================================
// Weight transpose (coalesced both sides) + zero the L1-stat accumulators.
// ===========================================================================
__global__ __launch_bounds__(256) void transpose_lc(
    const float* __restrict__ w1, const float* __restrict__ w2,
    const float* __restrict__ w3, const float* __restrict__ w4,
    const float* __restrict__ w5, const float* __restrict__ w6,
    float* __restrict__ t1, float* __restrict__ t2, float* __restrict__ t3,
    float* __restrict__ t4, float* __restrict__ t5, float* __restrict__ t6,
    float* __restrict__ accS, float* __restrict__ accQ) {
    if (blockIdx.x == 0 && threadIdx.x < 64) {
        accS[threadIdx.x] = 0.f;
        accQ[threadIdx.x] = 0.f;
    }
    __shared__ float s[32 * 49];
    int tile = blockIdx.x;
    const float* in; float* out; int N, K;
    if      (tile < 512) {             in = w1; out = t1; N = 16384; K = 49; }
    else if (tile < 640) { tile -= 512; in = w2; out = t2; N = 4096;  K = 25; }
    else if (tile < 768) { tile -= 640; in = w3; out = t3; N = 4096;  K = 25; }
    else if (tile < 800) { tile -= 768; in = w4; out = t4; N = 1024;  K = 9;  }
    else if (tile < 832) { tile -= 800; in = w5; out = t5; N = 1024;  K = 9;  }
    else                 { tile -= 832; in = w6; out = t6; N = 256;   K = 9;  }
    const int p0  = tile * 32;
    const int tot = 32 * K;
    const int tid = threadIdx.x;
    for (int idx = tid; idx < tot; idx += 256) s[idx] = in[(size_t)p0 * K + idx];
    __syncthreads();
    for (int idx = tid; idx < tot; idx += 256) {
        int k = idx >> 5, pl = idx & 31;
        out[(size_t)k * N + p0 + pl] = s[pl * K + k];
    }
}

// ===========================================================================
// Kernel A: L1 LC + ReLU + per-image LN stat accumulation (warp atomics).
// ===========================================================================
template <int RPB, int BCH>
__global__ __launch_bounds__(512) void lc1_kernel(const float* __restrict__ in,
                                                  const float* __restrict__ wt,
                                                  const float* __restrict__ bias,
                                                  float* __restrict__ act,
                                                  float* __restrict__ accS,
                                                  float* __restrict__ accQ) {
    constexpr int H = 128, W = 128, K = 7, PAD = 3, KK = 49, N = H * W;
    constexpr int IW = W + 2 * PAD;
    constexpr int IR = RPB + 2 * PAD;
    constexpr int NT = RPB * W;

    __shared__ float sin[IR * IW];

    const int r0  = blockIdx.x * RPB;
    const int b0  = blockIdx.y * BCH;
    const int tid = threadIdx.x;
    const int li  = tid / W;
    const int lj  = tid % W;
    const int pix = (r0 + li) * W + lj;

    float wr[KK];
#pragma unroll
    for (int t = 0; t < KK; t++) wr[t] = wt[(size_t)t * N + pix];
    const float bb = bias[pix];

    for (int bi = 0; bi < BCH; bi++) {
        const int b = b0 + bi;
        const float* inb = in + (size_t)b * N;
        __syncthreads();
        for (int idx = tid; idx < IR * IW; idx += NT) {
            int r = idx / IW, c = idx % IW;
            int gi = r0 - PAD + r, gj = c - PAD;
            float v = 0.f;
            if (gi >= 0 && gi < H && gj >= 0 && gj < W) v = inb[gi * W + gj];
            sin[idx] = v;
        }
        __syncthreads();

        float sum = bb;
#pragma unroll
        for (int kh = 0; kh < K; kh++)
#pragma unroll
            for (int kw = 0; kw < K; kw++)
                sum = fmaf(wr[kh * K + kw], sin[(li + kh) * IW + (lj + kw)], sum);

        float v = fmaxf(sum, 0.f);
        act[(size_t)b * N + pix] = v;

        float s = v, q = v * v;
#pragma unroll
        for (int o = 16; o > 0; o >>= 1) {
            s += __shfl_down_sync(0xffffffffu, s, o);
            q += __shfl_down_sync(0xffffffffu, q, o);
        }
        if ((tid & 31) == 0) {
            atomicAdd(&accS[b], s);
            atomicAdd(&accQ[b], q);
        }
    }
}

// ===========================================================================
// Kernel B: fused L1-norm..L6.  One block per image, 1024 threads.
// ===========================================================================
#define NTB 1024

// No leading guard sync: every call site has a __syncthreads between the
// previous call's red[] reads and this call's writes.
__device__ __forceinline__ void block_sum2(float& s, float& q, float* red) {
#pragma unroll
    for (int o = 16; o > 0; o >>= 1) {
        s += __shfl_down_sync(0xffffffffu, s, o);
        q += __shfl_down_sync(0xffffffffu, q, o);
    }
    const int wid = threadIdx.x >> 5, lane = threadIdx.x & 31;
    if (lane == 0) { red[wid] = s; red[32 + wid] = q; }
    __syncthreads();
    if (wid == 0) {
        s = red[lane]; q = red[32 + lane];
#pragma unroll
        for (int o = 16; o > 0; o >>= 1) {
            s += __shfl_down_sync(0xffffffffu, s, o);
            q += __shfl_down_sync(0xffffffffu, q, o);
        }
        if (lane == 0) { red[0] = s; red[32] = q; }
    }
    __syncthreads();
    s = red[0]; q = red[32];
}

__device__ __forceinline__ void lc64_v4(const float4* __restrict__ wt4,
                                        const float4* __restrict__ b4,
                                        const float* s_in, float* s_act,
                                        float& mean, float& rstd, float* red) {
    constexpr int PWIDTH = 68;
    const int tid = threadIdx.x;
    const int p0 = tid * 4;
    const int i = p0 >> 6, j = p0 & 63;
    const float* sp0 = s_in + i * PWIDTH + j;
    float4 acc = b4[tid];
#pragma unroll
    for (int kh = 0; kh < 5; kh++)
#pragma unroll
        for (int kw = 0; kw < 5; kw++) {
            float4 w = wt4[(size_t)(kh * 5 + kw) * 1024 + tid];
            const float* sp = sp0 + kh * PWIDTH + kw;
            acc.x = fmaf(w.x, sp[0], acc.x);
            acc.y = fmaf(w.y, sp[1], acc.y);
            acc.z = fmaf(w.z, sp[2], acc.z);
            acc.w = fmaf(w.w, sp[3], acc.w);
        }
    float4 v = make_float4(fmaxf(acc.x, 0.f), fmaxf(acc.y, 0.f),
                           fmaxf(acc.z, 0.f), fmaxf(acc.w, 0.f));
    ((float4*)s_act)[tid] = v;
    float s = v.x + v.y + v.z + v.w;
    float q = v.x * v.x + v.y * v.y + v.z * v.z + v.w * v.w;
    block_sum2(s, q, red);
    mean = s * (1.0f / 4096.0f);
    rstd = rsqrtf(q * (1.0f / 4096.0f) - mean * mean + 1e-5f);
}

template <int H, int PWIDTH>
__device__ __forceinline__ void lc_small(const float* __restrict__ wt,
                                         const float* __restrict__ bias,
                                         const float* s_in, float* s_act,
                                         float& mean, float& rstd, float* red) {
    constexpr int N = H * H;
    const int tid = threadIdx.x;
    float s = 0.f, q = 0.f;
    if (tid < N) {
        const int i = tid / H, j = tid % H;
        const float* sp0 = s_in + i * PWIDTH + j;
        float acc = bias[tid];
#pragma unroll
        for (int kh = 0; kh < 3; kh++)
#pragma unroll
            for (int kw = 0; kw < 3; kw++)
                acc = fmaf(wt[(size_t)(kh * 3 + kw) * N + tid],
                           sp0[kh * PWIDTH + kw], acc);
        float v = fmaxf(acc, 0.f);
        s_act[tid] = v;
        s = v; q = v * v;
    }
    block_sum2(s, q, red);
    mean = s * (1.0f / N);
    rstd = rsqrtf(q * (1.0f / N) - mean * mean + 1e-5f);
}

__global__ __launch_bounds__(NTB) void fused_kernel(
    const float* __restrict__ bufA,
    const float* __restrict__ accS, const float* __restrict__ accQ,
    const float* __restrict__ g1, const float* __restrict__ be1,
    const float4* __restrict__ wt2, const float4* __restrict__ b2,
    const float4* __restrict__ g2, const float4* __restrict__ be2,
    const float4* __restrict__ wt3, const float4* __restrict__ b3,
    const float* __restrict__ g3, const float* __restrict__ be3,
    const float* __restrict__ wt4, const float* __restrict__ b4,
    const float* __restrict__ g4, const float* __restrict__ be4,
    const float* __restrict__ wt5, const float* __restrict__ b5,
    const float* __restrict__ g5, const float* __restrict__ be5,
    const float* __restrict__ wt6, const float* __restrict__ b6,
    const float* __restrict__ g6, const float* __restrict__ be6,
    float* __restrict__ featT) {

    __shared__ __align__(16) float s_pad64[68 * 68];
    __shared__ __align__(16) float s_pad32[34 * 34];
    __shared__ __align__(16) float s_pad16[18 * 18];
    __shared__ __align__(16) float s_act[64 * 64];
    __shared__ float s_red[64];

    const int b   = blockIdx.x;
    const int tid = threadIdx.x;
    const float* ab = bufA + (size_t)b * 128 * 128;

    // zero halos (interiors fully rewritten each use)
    for (int p = tid; p < 68 * 68; p += NTB) s_pad64[p] = 0.f;
    for (int p = tid; p < 34 * 34; p += NTB) s_pad32[p] = 0.f;
    for (int p = tid; p < 18 * 18; p += NTB) s_pad16[p] = 0.f;
    __syncthreads();

    // ---------------- L1 norm + pool (stats from lc1 atomics) --------------
    {
        const float mean = accS[b] * (1.0f / 16384.0f);
        const float rstd = rsqrtf(accQ[b] * (1.0f / 16384.0f) - mean * mean + 1e-5f);
        for (int p = tid; p < 64 * 64; p += NTB) {
            const int oi = p >> 6, oj = p & 63;
            float m = -INFINITY;
#pragma unroll
            for (int di = 0; di < 2; di++)
#pragma unroll
                for (int dj = 0; dj < 2; dj++) {
                    const int idx = (2 * oi + di) * 128 + (2 * oj + dj);
                    float v = (ab[idx] - mean) * rstd * g1[idx] + be1[idx];
                    m = fmaxf(m, v);
                }
            s_pad64[(oi + 2) * 68 + (oj + 2)] = m;
        }
        __syncthreads();
    }

    float mean, rstd;

    // ---------------- L2 ----------------------------------------------------
    lc64_v4(wt2, b2, s_pad64, s_act, mean, rstd, s_red);
    {
        const int p0 = tid * 4;
        const int i = p0 >> 6, j = p0 & 63;
        float4 v = ((const float4*)s_act)[tid];
        float4 gg = g2[tid], bb = be2[tid];
        float* dst = s_pad64 + (i + 2) * 68 + (j + 2);
        dst[0] = (v.x - mean) * rstd * gg.x + bb.x;
        dst[1] = (v.y - mean) * rstd * gg.y + bb.y;
        dst[2] = (v.z - mean) * rstd * gg.z + bb.z;
        dst[3] = (v.w - mean) * rstd * gg.w + bb.w;
        __syncthreads();
    }

    // ---------------- L3 + pool -> s_pad32 ----------------------------------
    lc64_v4(wt3, b3, s_pad64, s_act, mean, rstd, s_red);
    {
        if (tid < 32 * 32) {
            const int oi = tid >> 5, oj = tid & 31;
            float m = -INFINITY;
#pragma unroll
            for (int di = 0; di < 2; di++)
#pragma unroll
                for (int dj = 0; dj < 2; dj++) {
                    const int idx = (2 * oi + di) * 64 + (2 * oj + dj);
                    float v = (s_act[idx] - mean) * rstd * g3[idx] + be3[idx];
                    m = fmaxf(m, v);
                }
            s_pad32[(oi + 1) * 34 + (oj + 1)] = m;
        }
        __syncthreads();
    }

    // ---------------- L4 ----------------------------------------------------
    lc_small<32, 34>(wt4, b4, s_pad32, s_act, mean, rstd, s_red);
    {
        if (tid < 32 * 32) {
            const int i = tid >> 5, j = tid & 31;
            s_pad32[(i + 1) * 34 + (j + 1)] =
                (s_act[tid] - mean) * rstd * g4[tid] + be4[tid];
        }
        __syncthreads();
    }

    // ---------------- L5 + pool -> s_pad16 ----------------------------------
    lc_small<32, 34>(wt5, b5, s_pad32, s_act, mean, rstd, s_red);
    {
        if (tid < 16 * 16) {
            const int oi = tid >> 4, oj = tid & 15;
            float m = -INFINITY;
#pragma unroll
            for (int di = 0; di < 2; di++)
#pragma unroll
                for (int dj = 0; dj < 2; dj++) {
                    const int idx = (2 * oi + di) * 32 + (2 * oj + dj);
                    float v = (s_act[idx] - mean) * rstd * g5[idx] + be5[idx];
                    m = fmaxf(m, v);
                }
            s_pad16[(oi + 1) * 18 + (oj + 1)] = m;
        }
        __syncthreads();
    }

    // ---------------- L6 -> transposed features to gmem ---------------------
    lc_small<16, 18>(wt6, b6, s_pad16, s_act, mean, rstd, s_red);
    if (tid < 256) {
        float v = (s_act[tid] - mean) * rstd * g6[tid] + be6[tid];
        featT[(size_t)tid * 64 + b] = v;   // [k][img]
    }
}

// ===========================================================================
// Kernel C: FC GEMM.  64 blocks x 16 outputs x all 64 images.
// Weights read ONCE chip-wide via smem staging.
// ===========================================================================
__global__ __launch_bounds__(256) void fc_gemm(const float4* __restrict__ featT4,
                                               const float* __restrict__ fcw,
                                               const float* __restrict__ fcb,
                                               float* __restrict__ logits) {
    __shared__ float  sw[16 * 257];     // [o_l][k], stride 257 (conflict-free)
    __shared__ float4 sf[64 * 16];      // [k_chunk][img_quad]
    const int tid = threadIdx.x;
    const int o0  = blockIdx.x * 16;
    const int o_l = tid >> 4;           // 0..15
    const int q   = tid & 15;           // image quad 0..15

    // stage this block's 16 weight rows (16 KB, coalesced)
    for (int idx = tid; idx < 16 * 256; idx += 256) {
        int r = idx >> 8, c = idx & 255;
        sw[r * 257 + c] = fcw[(size_t)(o0 + r) * 256 + c];
    }

    float4 acc = make_float4(0.f, 0.f, 0.f, 0.f);
#pragma unroll
    for (int k0 = 0; k0 < 256; k0 += 64) {
        __syncthreads();
        for (int idx = tid; idx < 64 * 16; idx += 256)
            sf[idx] = featT4[(size_t)(k0 << 4) + idx];
        __syncthreads();
#pragma unroll
        for (int k = 0; k < 64; k++) {
            float  w = sw[o_l * 257 + k0 + k];
            float4 f = sf[k * 16 + q];
            acc.x = fmaf(w, f.x, acc.x);
            acc.y = fmaf(w, f.y, acc.y);
            acc.z = fmaf(w, f.z, acc.z);
            acc.w = fmaf(w, f.w, acc.w);
        }
    }

    const float bb = fcb[o0 + o_l];
    const int img0 = q * 4;
    logits[(size_t)(img0 + 0) * 1024 + o0 + o_l] = acc.x + bb;
    logits[(size_t)(img0 + 1) * 1024 + o0 + o_l] = acc.y + bb;
    logits[(size_t)(img0 + 2) * 1024 + o0 + o_l] = acc.z + bb;
    logits[(size_t)(img0 + 3) * 1024 + o0 + o_l] = acc.w + bb;
}

// ===========================================================================
// Kernel D: softmax over 1024, one block per image.
// ===========================================================================
__global__ __launch_bounds__(256) void softmax_kernel(const float4* __restrict__ logits4,
                                                      float4* __restrict__ out4) {
    __shared__ float red[8];
    const int b = blockIdx.x, tid = threadIdx.x;
    const int wid = tid >> 5, lane = tid & 31;

    float4 l = logits4[(size_t)b * 256 + tid];
    float m = fmaxf(fmaxf(l.x, l.y), fmaxf(l.z, l.w));
#pragma unroll
    for (int o = 16; o > 0; o >>= 1)
        m = fmaxf(m, __shfl_xor_sync(0xffffffffu, m, o));
    if (lane == 0) red[wid] = m;
    __syncthreads();
    float M = red[0];
#pragma unroll
    for (int w = 1; w < 8; w++) M = fmaxf(M, red[w]);
    __syncthreads();

    float4 e = make_float4(__expf(l.x - M), __expf(l.y - M),
                           __expf(l.z - M), __expf(l.w - M));
    float s = e.x + e.y + e.z + e.w;
#pragma unroll
    for (int o = 16; o > 0; o >>= 1)
        s += __shfl_xor_sync(0xffffffffu, s, o);
    if (lane == 0) red[wid] = s;
    __syncthreads();
    float S = 0.f;
#pragma unroll
    for (int w = 0; w < 8; w++) S += red[w];
    const float R = 1.0f / S;

    out4[(size_t)b * 256 + tid] = make_float4(e.x * R, e.y * R, e.z * R, e.w * R);
}

// ===========================================================================
// Launch
// ===========================================================================
extern "C" void kernel_launch(void* const* d_in, const int* in_sizes, int n_in,
                              void* d_out, int out_size) {
    (void)in_sizes; (void)n_in; (void)out_size;

    const float* x   = (const float*)d_in[0];
    const float* w1  = (const float*)d_in[1];
    const float* b1  = (const float*)d_in[2];
    const float* g1  = (const float*)d_in[3];
    const float* be1 = (const float*)d_in[4];
    const float* w2  = (const float*)d_in[5];
    const float* b2  = (const float*)d_in[6];
    const float* g2  = (const float*)d_in[7];
    const float* be2 = (const float*)d_in[8];
    const float* w3  = (const float*)d_in[9];
    const float* b3  = (const float*)d_in[10];
    const float* g3  = (const float*)d_in[11];
    const float* be3 = (const float*)d_in[12];
    const float* w4  = (const float*)d_in[13];
    const float* b4  = (const float*)d_in[14];
    const float* g4  = (const float*)d_in[15];
    const float* be4 = (const float*)d_in[16];
    const float* w5  = (const float*)d_in[17];
    const float* b5  = (const float*)d_in[18];
    const float* g5  = (const float*)d_in[19];
    const float* be5 = (const float*)d_in[20];
    const float* w6  = (const float*)d_in[21];
    const float* b6  = (const float*)d_in[22];
    const float* g6  = (const float*)d_in[23];
    const float* be6 = (const float*)d_in[24];
    const float* fcw = (const float*)d_in[25];
    const float* fcb = (const float*)d_in[26];
    float* out = (float*)d_out;

    float *A, *t1, *t2, *t3, *t4, *t5, *t6, *ft, *lg, *aS, *aQ;
    cudaGetSymbolAddress((void**)&A,  g_bufA);
    cudaGetSymbolAddress((void**)&t1, g_wt1);
    cudaGetSymbolAddress((void**)&t2, g_wt2);
    cudaGetSymbolAddress((void**)&t3, g_wt3);
    cudaGetSymbolAddress((void**)&t4, g_wt4);
    cudaGetSymbolAddress((void**)&t5, g_wt5);
    cudaGetSymbolAddress((void**)&t6, g_wt6);
    cudaGetSymbolAddress((void**)&ft, g_featT);
    cudaGetSymbolAddress((void**)&lg, g_logits);
    cudaGetSymbolAddress((void**)&aS, g_accS);
    cudaGetSymbolAddress((void**)&aQ, g_accQ);

    transpose_lc<<<840, 256>>>(w1, w2, w3, w4, w5, w6,
                               t1, t2, t3, t4, t5, t6, aS, aQ);

    lc1_kernel<4, 8><<<dim3(32, 8), 512>>>(x, t1, b1, A, aS, aQ);

    fused_kernel<<<64, NTB>>>(A, aS, aQ,
        g1, be1,
        (const float4*)t2, (const float4*)b2, (const float4*)g2, (const float4*)be2,
        (const float4*)t3, (const float4*)b3, g3, be3,
        t4, b4, g4, be4, t5, b5, g5, be5, t6, b6, g6, be6,
        ft);

    fc_gemm<<<64, 256>>>((const float4*)ft, fcw, fcb, lg);
    softmax_kernel<<<64, 256>>>((const float4*)lg, (float4*)out);
}

// round 9
// speedup vs baseline: 1.2052x; 1.0951x over previous
#include <cuda_runtime.h>
#include <cuda_bf16.h>
#include <math.h>

// ---------------------------------------------------------------------------
// Scratch (allocation-free device globals)
// ---------------------------------------------------------------------------
__device__ float g_bufA[64 * 128 * 128];                  // pre-norm L1 acts
__device__ float g_bufB[64 * 64 * 64];                    // pre-norm L2 acts
__device__ float g_bufC[64 * 64 * 64];                    // pre-norm L3 acts
__device__ __align__(16) float g_wt1[16384 * 49];         // [k][pix]
__device__ __align__(16) float g_wt2[4096 * 25];
__device__ __align__(16) float g_wt3[4096 * 25];
__device__ __align__(16) float g_wt4[1024 * 9];
__device__ __align__(16) float g_wt5[1024 * 9];
__device__ __align__(16) float g_wt6[256 * 9];
__device__ __align__(16) float g_featT[256 * 64];         // [k][img]
__device__ __align__(16) float g_logits[64 * 1024];
__device__ float g_acc[6 * 64];                           // S1,Q1,S2,Q2,S3,Q3

// ===========================================================================
// Weight transpose (coalesced both sides) + zero the stat accumulators.
// ===========================================================================
__global__ __launch_bounds__(256) void transpose_lc(
    const float* __restrict__ w1, const float* __restrict__ w2,
    const float* __restrict__ w3, const float* __restrict__ w4,
    const float* __restrict__ w5, const float* __restrict__ w6,
    float* __restrict__ t1, float* __restrict__ t2, float* __restrict__ t3,
    float* __restrict__ t4, float* __restrict__ t5, float* __restrict__ t6,
    float* __restrict__ acc) {
    if (blockIdx.x == 0)
        for (int i = threadIdx.x; i < 6 * 64; i += 256) acc[i] = 0.f;
    __shared__ float s[32 * 49];
    int tile = blockIdx.x;
    const float* in; float* out; int N, K;
    if      (tile < 512) {             in = w1; out = t1; N = 16384; K = 49; }
    else if (tile < 640) { tile -= 512; in = w2; out = t2; N = 4096;  K = 25; }
    else if (tile < 768) { tile -= 640; in = w3; out = t3; N = 4096;  K = 25; }
    else if (tile < 800) { tile -= 768; in = w4; out = t4; N = 1024;  K = 9;  }
    else if (tile < 832) { tile -= 800; in = w5; out = t5; N = 1024;  K = 9;  }
    else                 { tile -= 832; in = w6; out = t6; N = 256;   K = 9;  }
    const int p0  = tile * 32;
    const int tot = 32 * K;
    const int tid = threadIdx.x;
    for (int idx = tid; idx < tot; idx += 256) s[idx] = in[(size_t)p0 * K + idx];
    __syncthreads();
    for (int idx = tid; idx < tot; idx += 256) {
        int k = idx >> 5, pl = idx & 31;
        out[(size_t)k * N + p0 + pl] = s[pl * K + k];
    }
}

// ===========================================================================
// L1: LC 7x7 on 128x128 + ReLU + stat atomics. 256 blocks x 512 thr.
// ===========================================================================
template <int RPB, int BCH>
__global__ __launch_bounds__(512) void lc1_kernel(const float* __restrict__ in,
                                                  const float* __restrict__ wt,
                                                  const float* __restrict__ bias,
                                                  float* __restrict__ act,
                                                  float* __restrict__ accS,
                                                  float* __restrict__ accQ) {
    constexpr int H = 128, W = 128, K = 7, PAD = 3, KK = 49, N = H * W;
    constexpr int IW = W + 2 * PAD;
    constexpr int IR = RPB + 2 * PAD;
    constexpr int NT = RPB * W;

    __shared__ float sin[IR * IW];
    __shared__ float sred[32];

    const int r0  = blockIdx.x * RPB;
    const int b0  = blockIdx.y * BCH;
    const int tid = threadIdx.x;
    const int li  = tid / W;
    const int lj  = tid % W;
    const int pix = (r0 + li) * W + lj;

    float wr[KK];
#pragma unroll
    for (int t = 0; t < KK; t++) wr[t] = wt[(size_t)t * N + pix];
    const float bb = bias[pix];

    for (int bi = 0; bi < BCH; bi++) {
        const int b = b0 + bi;
        const float* inb = in + (size_t)b * N;
        __syncthreads();
        for (int idx = tid; idx < IR * IW; idx += NT) {
            int r = idx / IW, c = idx % IW;
            int gi = r0 - PAD + r, gj = c - PAD;
            float v = 0.f;
            if (gi >= 0 && gi < H && gj >= 0 && gj < W) v = inb[gi * W + gj];
            sin[idx] = v;
        }
        __syncthreads();

        float sum = bb;
#pragma unroll
        for (int kh = 0; kh < K; kh++)
#pragma unroll
            for (int kw = 0; kw < K; kw++)
                sum = fmaf(wr[kh * K + kw], sin[(li + kh) * IW + (lj + kw)], sum);

        float v = fmaxf(sum, 0.f);
        act[(size_t)b * N + pix] = v;

        float s = v, q = v * v;
#pragma unroll
        for (int o = 16; o > 0; o >>= 1) {
            s += __shfl_down_sync(0xffffffffu, s, o);
            q += __shfl_down_sync(0xffffffffu, q, o);
        }
        const int wid = tid >> 5;
        if ((tid & 31) == 0) { sred[wid] = s; sred[16 + wid] = q; }
        __syncthreads();
        if (tid == 0) {
            float ts = 0.f, tq = 0.f;
#pragma unroll
            for (int k = 0; k < 16; k++) { ts += sred[k]; tq += sred[16 + k]; }
            atomicAdd(&accS[b], ts);
            atomicAdd(&accQ[b], tq);
        }
    }
}

// ===========================================================================
// L2 / L3: LC 5x5 on 64x64.  Input staged with previous-layer norm (+pool for
// L2) applied on the fly using the previous layer's atomic stats.
// Block: 4 rows x 64 cols = 256 thr, BCH images.  Weights in registers.
// ===========================================================================
template <bool POOLIN, int BCH>
__global__ __launch_bounds__(256) void lc64_kernel(
    const float* __restrict__ prevAct,   // POOLIN: [b][128][128] else [b][64][64]
    const float* __restrict__ accSp, const float* __restrict__ accQp,
    const float* __restrict__ gp, const float* __restrict__ bep,
    const float* __restrict__ wt, const float* __restrict__ bias,
    float* __restrict__ act,
    float* __restrict__ accSo, float* __restrict__ accQo) {
    constexpr int H = 64, K = 5, PAD = 2, KK = 25, N = H * H;
    constexpr int RPB = 4, NT = 256;
    constexpr int IW = H + 2 * PAD;      // 68
    constexpr int IR = RPB + 2 * PAD;    // 8
    constexpr float INV_PREV = POOLIN ? (1.0f / 16384.0f) : (1.0f / 4096.0f);

    __shared__ float sin[IR * IW];
    __shared__ float sred[16];

    const int r0  = blockIdx.x * RPB;
    const int b0  = blockIdx.y * BCH;
    const int tid = threadIdx.x;
    const int li  = tid >> 6;
    const int lj  = tid & 63;
    const int pix = (r0 + li) * H + lj;

    float wr[KK];
#pragma unroll
    for (int t = 0; t < KK; t++) wr[t] = wt[(size_t)t * N + pix];
    const float bb = bias[pix];

    for (int bi = 0; bi < BCH; bi++) {
        const int b = b0 + bi;
        const float mean = accSp[b] * INV_PREV;
        const float rstd = rsqrtf(accQp[b] * INV_PREV - mean * mean + 1e-5f);

        __syncthreads();
        // stage normalized(+pooled) input tile
        for (int idx = tid; idx < IR * IW; idx += NT) {
            const int r = idx / IW, c = idx % IW;
            const int oi = r0 - PAD + r, oj = c - PAD;
            float v = 0.f;
            if (oi >= 0 && oi < H && oj >= 0 && oj < H) {
                if (POOLIN) {
                    const float* ab = prevAct + (size_t)b * 16384;
                    float m = -INFINITY;
#pragma unroll
                    for (int di = 0; di < 2; di++)
#pragma unroll
                        for (int dj = 0; dj < 2; dj++) {
                            const int idx1 = (2 * oi + di) * 128 + (2 * oj + dj);
                            float t = (ab[idx1] - mean) * rstd * gp[idx1] + bep[idx1];
                            m = fmaxf(m, t);
                        }
                    v = m;
                } else {
                    const int idx1 = oi * H + oj;
                    v = (prevAct[(size_t)b * N + idx1] - mean) * rstd * gp[idx1] + bep[idx1];
                }
            }
            sin[idx] = v;
        }
        __syncthreads();

        float sum = bb;
#pragma unroll
        for (int kh = 0; kh < K; kh++)
#pragma unroll
            for (int kw = 0; kw < K; kw++)
                sum = fmaf(wr[kh * K + kw], sin[(li + kh) * IW + (lj + kw)], sum);

        float v = fmaxf(sum, 0.f);
        act[(size_t)b * N + pix] = v;

        float s = v, q = v * v;
#pragma unroll
        for (int o = 16; o > 0; o >>= 1) {
            s += __shfl_down_sync(0xffffffffu, s, o);
            q += __shfl_down_sync(0xffffffffu, q, o);
        }
        const int wid = tid >> 5;
        if ((tid & 31) == 0) { sred[wid] = s; sred[8 + wid] = q; }
        __syncthreads();
        if (tid == 0) {
            float ts = 0.f, tq = 0.f;
#pragma unroll
            for (int k = 0; k < 8; k++) { ts += sred[k]; tq += sred[8 + k]; }
            atomicAdd(&accSo[b], ts);
            atomicAdd(&accQo[b], tq);
        }
    }
}

// ===========================================================================
// Tail: norm3+pool, L4, L5, L6 -> featT.  One block per image, 1024 threads.
// ===========================================================================
#define NTB 1024

__device__ __forceinline__ void block_sum2(float& s, float& q, float* red) {
#pragma unroll
    for (int o = 16; o > 0; o >>= 1) {
        s += __shfl_down_sync(0xffffffffu, s, o);
        q += __shfl_down_sync(0xffffffffu, q, o);
    }
    const int wid = threadIdx.x >> 5, lane = threadIdx.x & 31;
    if (lane == 0) { red[wid] = s; red[32 + wid] = q; }
    __syncthreads();
    if (wid == 0) {
        s = red[lane]; q = red[32 + lane];
#pragma unroll
        for (int o = 16; o > 0; o >>= 1) {
            s += __shfl_down_sync(0xffffffffu, s, o);
            q += __shfl_down_sync(0xffffffffu, q, o);
        }
        if (lane == 0) { red[0] = s; red[32] = q; }
    }
    __syncthreads();
    s = red[0]; q = red[32];
}

template <int H, int PWIDTH>
__device__ __forceinline__ void lc_small(const float* __restrict__ wt,
                                         const float* __restrict__ bias,
                                         const float* s_in, float* s_act,
                                         float& mean, float& rstd, float* red) {
    constexpr int N = H * H;
    const int tid = threadIdx.x;
    float s = 0.f, q = 0.f;
    if (tid < N) {
        const int i = tid / H, j = tid % H;
        const float* sp0 = s_in + i * PWIDTH + j;
        float acc = bias[tid];
#pragma unroll
        for (int kh = 0; kh < 3; kh++)
#pragma unroll
            for (int kw = 0; kw < 3; kw++)
                acc = fmaf(wt[(size_t)(kh * 3 + kw) * N + tid],
                           sp0[kh * PWIDTH + kw], acc);
        float v = fmaxf(acc, 0.f);
        s_act[tid] = v;
        s = v; q = v * v;
    }
    block_sum2(s, q, red);
    mean = s * (1.0f / N);
    rstd = rsqrtf(q * (1.0f / N) - mean * mean + 1e-5f);
}

__global__ __launch_bounds__(NTB) void tail_kernel(
    const float* __restrict__ act3,
    const float* __restrict__ accS3, const float* __restrict__ accQ3,
    const float* __restrict__ g3, const float* __restrict__ be3,
    const float* __restrict__ wt4, const float* __restrict__ b4,
    const float* __restrict__ g4, const float* __restrict__ be4,
    const float* __restrict__ wt5, const float* __restrict__ b5,
    const float* __restrict__ g5, const float* __restrict__ be5,
    const float* __restrict__ wt6, const float* __restrict__ b6,
    const float* __restrict__ g6, const float* __restrict__ be6,
    float* __restrict__ featT) {

    __shared__ __align__(16) float s_pad32[34 * 34];
    __shared__ __align__(16) float s_pad16[18 * 18];
    __shared__ __align__(16) float s_act[32 * 32];
    __shared__ float s_red[64];

    const int b   = blockIdx.x;
    const int tid = threadIdx.x;
    const float* ab = act3 + (size_t)b * 4096;

    for (int p = tid; p < 34 * 34; p += NTB) s_pad32[p] = 0.f;
    for (int p = tid; p < 18 * 18; p += NTB) s_pad16[p] = 0.f;
    __syncthreads();

    // ---- norm3 + pool -> s_pad32 ----
    {
        const float mean = accS3[b] * (1.0f / 4096.0f);
        const float rstd = rsqrtf(accQ3[b] * (1.0f / 4096.0f) - mean * mean + 1e-5f);
        if (tid < 32 * 32) {
            const int oi = tid >> 5, oj = tid & 31;
            float m = -INFINITY;
#pragma unroll
            for (int di = 0; di < 2; di++)
#pragma unroll
                for (int dj = 0; dj < 2; dj++) {
                    const int idx = (2 * oi + di) * 64 + (2 * oj + dj);
                    float v = (ab[idx] - mean) * rstd * g3[idx] + be3[idx];
                    m = fmaxf(m, v);
                }
            s_pad32[(oi + 1) * 34 + (oj + 1)] = m;
        }
        __syncthreads();
    }

    float mean, rstd;

    // ---- L4 ----
    lc_small<32, 34>(wt4, b4, s_pad32, s_act, mean, rstd, s_red);
    if (tid < 32 * 32) {
        const int i = tid >> 5, j = tid & 31;
        s_pad32[(i + 1) * 34 + (j + 1)] =
            (s_act[tid] - mean) * rstd * g4[tid] + be4[tid];
    }
    __syncthreads();

    // ---- L5 + pool ----
    lc_small<32, 34>(wt5, b5, s_pad32, s_act, mean, rstd, s_red);
    if (tid < 16 * 16) {
        const int oi = tid >> 4, oj = tid & 15;
        float m = -INFINITY;
#pragma unroll
        for (int di = 0; di < 2; di++)
#pragma unroll
            for (int dj = 0; dj < 2; dj++) {
                const int idx = (2 * oi + di) * 32 + (2 * oj + dj);
                float v = (s_act[idx] - mean) * rstd * g5[idx] + be5[idx];
                m = fmaxf(m, v);
            }
        s_pad16[(oi + 1) * 18 + (oj + 1)] = m;
    }
    __syncthreads();

    // ---- L6 -> featT ----
    lc_small<16, 18>(wt6, b6, s_pad16, s_act, mean, rstd, s_red);
    if (tid < 256) {
        float v = (s_act[tid] - mean) * rstd * g6[tid] + be6[tid];
        featT[(size_t)tid * 64 + b] = v;
    }
}

// ===========================================================================
// FC GEMM: 256 blocks x 4 outputs x 64 images.  Weights read once chip-wide.
// ===========================================================================
__global__ __launch_bounds__(256) void fc_gemm(const float4* __restrict__ featT4,
                                               const float* __restrict__ fcw,
                                               const float* __restrict__ fcb,
                                               float* __restrict__ logits) {
    __shared__ float sw[4 * 256];
    __shared__ __align__(16) float sf[128 * 64];
    const int tid = threadIdx.x;
    const int o0  = blockIdx.x * 4;
    const int o_l = tid >> 6;
    const int img = tid & 63;

    for (int idx = tid; idx < 1024; idx += 256)
        sw[idx] = fcw[(size_t)o0 * 256 + idx];

    float acc = fcb[o0 + o_l];
#pragma unroll
    for (int k0 = 0; k0 < 256; k0 += 128) {
        __syncthreads();
        float4* sf4 = (float4*)sf;
        for (int idx = tid; idx < 128 * 16; idx += 256)
            sf4[idx] = featT4[(size_t)k0 * 16 + idx];
        __syncthreads();
#pragma unroll 8
        for (int k = 0; k < 128; k++)
            acc = fmaf(sw[o_l * 256 + k0 + k], sf[k * 64 + img], acc);
    }
    logits[(size_t)img * 1024 + o0 + o_l] = acc;
}

// ===========================================================================
// Softmax over 1024, one block per image.
// ===========================================================================
__global__ __launch_bounds__(256) void softmax_kernel(const float4* __restrict__ logits4,
                                                      float4* __restrict__ out4) {
    __shared__ float red[8];
    const int b = blockIdx.x, tid = threadIdx.x;
    const int wid = tid >> 5, lane = tid & 31;

    float4 l = logits4[(size_t)b * 256 + tid];
    float m = fmaxf(fmaxf(l.x, l.y), fmaxf(l.z, l.w));
#pragma unroll
    for (int o = 16; o > 0; o >>= 1)
        m = fmaxf(m, __shfl_xor_sync(0xffffffffu, m, o));
    if (lane == 0) red[wid] = m;
    __syncthreads();
    float M = red[0];
#pragma unroll
    for (int w = 1; w < 8; w++) M = fmaxf(M, red[w]);
    __syncthreads();

    float4 e = make_float4(__expf(l.x - M), __expf(l.y - M),
                           __expf(l.z - M), __expf(l.w - M));
    float s = e.x + e.y + e.z + e.w;
#pragma unroll
    for (int o = 16; o > 0; o >>= 1)
        s += __shfl_xor_sync(0xffffffffu, s, o);
    if (lane == 0) red[wid] = s;
    __syncthreads();
    float S = 0.f;
#pragma unroll
    for (int w = 0; w < 8; w++) S += red[w];
    const float R = 1.0f / S;

    out4[(size_t)b * 256 + tid] = make_float4(e.x * R, e.y * R, e.z * R, e.w * R);
}

// ===========================================================================
// Launch
// ===========================================================================
extern "C" void kernel_launch(void* const* d_in, const int* in_sizes, int n_in,
                              void* d_out, int out_size) {
    (void)in_sizes; (void)n_in; (void)out_size;

    const float* x   = (const float*)d_in[0];
    const float* w1  = (const float*)d_in[1];
    const float* b1  = (const float*)d_in[2];
    const float* g1  = (const float*)d_in[3];
    const float* be1 = (const float*)d_in[4];
    const float* w2  = (const float*)d_in[5];
    const float* b2  = (const float*)d_in[6];
    const float* g2  = (const float*)d_in[7];
    const float* be2 = (const float*)d_in[8];
    const float* w3  = (const float*)d_in[9];
    const float* b3  = (const float*)d_in[10];
    const float* g3  = (const float*)d_in[11];
    const float* be3 = (const float*)d_in[12];
    const float* w4  = (const float*)d_in[13];
    const float* b4  = (const float*)d_in[14];
    const float* g4  = (const float*)d_in[15];
    const float* be4 = (const float*)d_in[16];
    const float* w5  = (const float*)d_in[17];
    const float* b5  = (const float*)d_in[18];
    const float* g5  = (const float*)d_in[19];
    const float* be5 = (const float*)d_in[20];
    const float* w6  = (const float*)d_in[21];
    const float* b6  = (const float*)d_in[22];
    const float* g6  = (const float*)d_in[23];
    const float* be6 = (const float*)d_in[24];
    const float* fcw = (const float*)d_in[25];
    const float* fcb = (const float*)d_in[26];
    float* out = (float*)d_out;

    float *A, *B, *C, *t1, *t2, *t3, *t4, *t5, *t6, *ft, *lg, *acc;
    cudaGetSymbolAddress((void**)&A,   g_bufA);
    cudaGetSymbolAddress((void**)&B,   g_bufB);
    cudaGetSymbolAddress((void**)&C,   g_bufC);
    cudaGetSymbolAddress((void**)&t1,  g_wt1);
    cudaGetSymbolAddress((void**)&t2,  g_wt2);
    cudaGetSymbolAddress((void**)&t3,  g_wt3);
    cudaGetSymbolAddress((void**)&t4,  g_wt4);
    cudaGetSymbolAddress((void**)&t5,  g_wt5);
    cudaGetSymbolAddress((void**)&t6,  g_wt6);
    cudaGetSymbolAddress((void**)&ft,  g_featT);
    cudaGetSymbolAddress((void**)&lg,  g_logits);
    cudaGetSymbolAddress((void**)&acc, g_acc);

    float* aS1 = acc;       float* aQ1 = acc + 64;
    float* aS2 = acc + 128; float* aQ2 = acc + 192;
    float* aS3 = acc + 256; float* aQ3 = acc + 320;

    transpose_lc<<<840, 256>>>(w1, w2, w3, w4, w5, w6,
                               t1, t2, t3, t4, t5, t6, acc);

    lc1_kernel<4, 8><<<dim3(32, 8), 512>>>(x, t1, b1, A, aS1, aQ1);

    // L2: input = norm1(pool(bufA)); output act2 -> B
    lc64_kernel<true, 8><<<dim3(16, 8), 256>>>(A, aS1, aQ1, g1, be1,
                                               t2, b2, B, aS2, aQ2);

    // L3: input = norm2(bufB); output act3 -> C
    lc64_kernel<false, 8><<<dim3(16, 8), 256>>>(B, aS2, aQ2, g2, be2,
                                                t3, b3, C, aS3, aQ3);

    tail_kernel<<<64, NTB>>>(C, aS3, aQ3, g3, be3,
                             t4, b4, g4, be4, t5, b5, g5, be5,
                             t6, b6, g6, be6, ft);

    fc_gemm<<<256, 256>>>((const float4*)ft, fcw, fcb, lg);
    softmax_kernel<<<64, 256>>>((const float4*)lg, (float4*)out);
}

// round 11
// speedup vs baseline: 1.3885x; 1.1521x over previous
#include <cuda_runtime.h>
#include <cuda_bf16.h>
#include <math.h>

// ---------------------------------------------------------------------------
// Scratch (allocation-free device globals)
// ---------------------------------------------------------------------------
__device__ float g_bufA[64 * 128 * 128];                  // pre-norm L1 acts
__device__ float g_bufB[64 * 64 * 64];                    // pre-norm L2 acts
__device__ float g_bufC[64 * 64 * 64];                    // pre-norm L3 acts
__device__ __align__(16) float g_wt1[16384 * 49];         // [k][pix]
__device__ __align__(16) float g_wt2[4096 * 25];
__device__ __align__(16) float g_wt3[4096 * 25];
__device__ __align__(16) float g_wt4[1024 * 9];
__device__ __align__(16) float g_wt5[1024 * 9];
__device__ __align__(16) float g_wt6[256 * 9];
__device__ __align__(16) float g_featT[256 * 64];         // [k][img]
__device__ __align__(16) float g_logits[64 * 1024];
__device__ float g_acc[6 * 64];                           // S1,Q1,S2,Q2,S3,Q3

// ===========================================================================
// Weight transpose (coalesced both sides) + zero the stat accumulators.
// ===========================================================================
__global__ __launch_bounds__(256) void transpose_lc(
    const float* __restrict__ w1, const float* __restrict__ w2,
    const float* __restrict__ w3, const float* __restrict__ w4,
    const float* __restrict__ w5, const float* __restrict__ w6,
    float* __restrict__ t1, float* __restrict__ t2, float* __restrict__ t3,
    float* __restrict__ t4, float* __restrict__ t5, float* __restrict__ t6,
    float* __restrict__ acc) {
    if (blockIdx.x == 0)
        for (int i = threadIdx.x; i < 6 * 64; i += 256) acc[i] = 0.f;
    __shared__ float s[32 * 49];
    int tile = blockIdx.x;
    const float* in; float* out; int N, K;
    if      (tile < 512) {             in = w1; out = t1; N = 16384; K = 49; }
    else if (tile < 640) { tile -= 512; in = w2; out = t2; N = 4096;  K = 25; }
    else if (tile < 768) { tile -= 640; in = w3; out = t3; N = 4096;  K = 25; }
    else if (tile < 800) { tile -= 768; in = w4; out = t4; N = 1024;  K = 9;  }
    else if (tile < 832) { tile -= 800; in = w5; out = t5; N = 1024;  K = 9;  }
    else                 { tile -= 832; in = w6; out = t6; N = 256;   K = 9;  }
    const int p0  = tile * 32;
    const int tot = 32 * K;
    const int tid = threadIdx.x;
    for (int idx = tid; idx < tot; idx += 256) s[idx] = in[(size_t)p0 * K + idx];
    __syncthreads();
    for (int idx = tid; idx < tot; idx += 256) {
        int k = idx >> 5, pl = idx & 31;
        out[(size_t)k * N + p0 + pl] = s[pl * K + k];
    }
}

// ===========================================================================
// L1: LC 7x7 on 128x128 + ReLU + stat atomics. 256 blocks x 512 thr.
// Weights in registers, reused across BCH images (3.2 MB tensor => reuse pays).
// ===========================================================================
template <int RPB, int BCH>
__global__ __launch_bounds__(512) void lc1_kernel(const float* __restrict__ in,
                                                  const float* __restrict__ wt,
                                                  const float* __restrict__ bias,
                                                  float* __restrict__ act,
                                                  float* __restrict__ accS,
                                                  float* __restrict__ accQ) {
    constexpr int H = 128, W = 128, K = 7, PAD = 3, KK = 49, N = H * W;
    constexpr int IW = W + 2 * PAD;
    constexpr int IR = RPB + 2 * PAD;
    constexpr int NT = RPB * W;

    __shared__ float sin[IR * IW];
    __shared__ float sred[32];

    const int r0  = blockIdx.x * RPB;
    const int b0  = blockIdx.y * BCH;
    const int tid = threadIdx.x;
    const int li  = tid / W;
    const int lj  = tid % W;
    const int pix = (r0 + li) * W + lj;

    float wr[KK];
#pragma unroll
    for (int t = 0; t < KK; t++) wr[t] = wt[(size_t)t * N + pix];
    const float bb = bias[pix];

    for (int bi = 0; bi < BCH; bi++) {
        const int b = b0 + bi;
        const float* inb = in + (size_t)b * N;
        __syncthreads();
        for (int idx = tid; idx < IR * IW; idx += NT) {
            int r = idx / IW, c = idx % IW;
            int gi = r0 - PAD + r, gj = c - PAD;
            float v = 0.f;
            if (gi >= 0 && gi < H && gj >= 0 && gj < W) v = inb[gi * W + gj];
            sin[idx] = v;
        }
        __syncthreads();

        float sum = bb;
#pragma unroll
        for (int kh = 0; kh < K; kh++)
#pragma unroll
            for (int kw = 0; kw < K; kw++)
                sum = fmaf(wr[kh * K + kw], sin[(li + kh) * IW + (lj + kw)], sum);

        float v = fmaxf(sum, 0.f);
        act[(size_t)b * N + pix] = v;

        float s = v, q = v * v;
#pragma unroll
        for (int o = 16; o > 0; o >>= 1) {
            s += __shfl_down_sync(0xffffffffu, s, o);
            q += __shfl_down_sync(0xffffffffu, q, o);
        }
        const int wid = tid >> 5;
        if ((tid & 31) == 0) { sred[wid] = s; sred[16 + wid] = q; }
        __syncthreads();
        if (tid == 0) {
            float ts = 0.f, tq = 0.f;
#pragma unroll
            for (int k = 0; k < 16; k++) { ts += sred[k]; tq += sred[16 + k]; }
            atomicAdd(&accS[b], ts);
            atomicAdd(&accQ[b], tq);
        }
    }
}

// ===========================================================================
// L2 / L3: LC 5x5 on 64x64, one block = (4 rows x 64 cols, ONE image).
// Grid (16, 64) = 1024 blocks -> high occupancy, no serial image loop.
// Input staged with previous-layer norm (+pool for L2) on the fly.
// ===========================================================================
template <bool POOLIN>
__global__ __launch_bounds__(256) void lc64_kernel(
    const float* __restrict__ prevAct,
    const float* __restrict__ accSp, const float* __restrict__ accQp,
    const float* __restrict__ gp, const float* __restrict__ bep,
    const float* __restrict__ wt, const float* __restrict__ bias,
    float* __restrict__ act,
    float* __restrict__ accSo, float* __restrict__ accQo) {
    constexpr int H = 64, K = 5, PAD = 2, KK = 25, N = H * H;
    constexpr int RPB = 4, NT = 256;
    constexpr int IW = H + 2 * PAD;      // 68
    constexpr int IR = RPB + 2 * PAD;    // 8
    constexpr float INV_PREV = POOLIN ? (1.0f / 16384.0f) : (1.0f / 4096.0f);

    __shared__ float sin[IR * IW];
    __shared__ float sred[16];

    const int r0  = blockIdx.x * RPB;
    const int b   = blockIdx.y;
    const int tid = threadIdx.x;
    const int li  = tid >> 6;
    const int lj  = tid & 63;
    const int pix = (r0 + li) * H + lj;

    const float mean = accSp[b] * INV_PREV;
    const float rstd = rsqrtf(accQp[b] * INV_PREV - mean * mean + 1e-5f);

    // stage normalized(+pooled) input tile
    for (int idx = tid; idx < IR * IW; idx += NT) {
        const int r = idx / IW, c = idx % IW;
        const int oi = r0 - PAD + r, oj = c - PAD;
        float v = 0.f;
        if (oi >= 0 && oi < H && oj >= 0 && oj < H) {
            if (POOLIN) {
                const float* ab = prevAct + (size_t)b * 16384;
                float m = -INFINITY;
#pragma unroll
                for (int di = 0; di < 2; di++)
#pragma unroll
                    for (int dj = 0; dj < 2; dj++) {
                        const int idx1 = (2 * oi + di) * 128 + (2 * oj + dj);
                        float t = (ab[idx1] - mean) * rstd * gp[idx1] + bep[idx1];
                        m = fmaxf(m, t);
                    }
                v = m;
            } else {
                const int idx1 = oi * H + oj;
                v = (prevAct[(size_t)b * N + idx1] - mean) * rstd * gp[idx1] + bep[idx1];
            }
        }
        sin[idx] = v;
    }

    // weight loads overlap the staging (independent streams)
    float wr[KK];
#pragma unroll
    for (int t = 0; t < KK; t++) wr[t] = wt[(size_t)t * N + pix];
    const float bb = bias[pix];
    __syncthreads();

    float sum = bb;
#pragma unroll
    for (int kh = 0; kh < K; kh++)
#pragma unroll
        for (int kw = 0; kw < K; kw++)
            sum = fmaf(wr[kh * K + kw], sin[(li + kh) * IW + (lj + kw)], sum);

    float v = fmaxf(sum, 0.f);
    act[(size_t)b * N + pix] = v;

    float s = v, q = v * v;
#pragma unroll
    for (int o = 16; o > 0; o >>= 1) {
        s += __shfl_down_sync(0xffffffffu, s, o);
        q += __shfl_down_sync(0xffffffffu, q, o);
    }
    const int wid = tid >> 5;
    if ((tid & 31) == 0) { sred[wid] = s; sred[8 + wid] = q; }
    __syncthreads();
    if (tid == 0) {
        float ts = 0.f, tq = 0.f;
#pragma unroll
        for (int k = 0; k < 8; k++) { ts += sred[k]; tq += sred[8 + k]; }
        atomicAdd(&accSo[b], ts);
        atomicAdd(&accQo[b], tq);
    }
}

// ===========================================================================
// Tail: norm3+pool, L4, L5, L6 -> featT.  One block per image, 1024 threads.
// ===========================================================================
#define NTB 1024

__device__ __forceinline__ void block_sum2(float& s, float& q, float* red) {
#pragma unroll
    for (int o = 16; o > 0; o >>= 1) {
        s += __shfl_down_sync(0xffffffffu, s, o);
        q += __shfl_down_sync(0xffffffffu, q, o);
    }
    const int wid = threadIdx.x >> 5, lane = threadIdx.x & 31;
    if (lane == 0) { red[wid] = s; red[32 + wid] = q; }
    __syncthreads();
    if (wid == 0) {
        s = red[lane]; q = red[32 + lane];
#pragma unroll
        for (int o = 16; o > 0; o >>= 1) {
            s += __shfl_down_sync(0xffffffffu, s, o);
            q += __shfl_down_sync(0xffffffffu, q, o);
        }
        if (lane == 0) { red[0] = s; red[32] = q; }
    }
    __syncthreads();
    s = red[0]; q = red[32];
}

template <int H, int PWIDTH>
__device__ __forceinline__ void lc_small(const float* __restrict__ wt,
                                         const float* __restrict__ bias,
                                         const float* s_in, float* s_act,
                                         float& mean, float& rstd, float* red) {
    constexpr int N = H * H;
    const int tid = threadIdx.x;
    float s = 0.f, q = 0.f;
    if (tid < N) {
        const int i = tid / H, j = tid % H;
        const float* sp0 = s_in + i * PWIDTH + j;
        float acc = bias[tid];
#pragma unroll
        for (int kh = 0; kh < 3; kh++)
#pragma unroll
            for (int kw = 0; kw < 3; kw++)
                acc = fmaf(wt[(size_t)(kh * 3 + kw) * N + tid],
                           sp0[kh * PWIDTH + kw], acc);
        float v = fmaxf(acc, 0.f);
        s_act[tid] = v;
        s = v; q = v * v;
    }
    block_sum2(s, q, red);
    mean = s * (1.0f / N);
    rstd = rsqrtf(q * (1.0f / N) - mean * mean + 1e-5f);
}

__global__ __launch_bounds__(NTB) void tail_kernel(
    const float* __restrict__ act3,
    const float* __restrict__ accS3, const float* __restrict__ accQ3,
    const float* __restrict__ g3, const float* __restrict__ be3,
    const float* __restrict__ wt4, const float* __restrict__ b4,
    const float* __restrict__ g4, const float* __restrict__ be4,
    const float* __restrict__ wt5, const float* __restrict__ b5,
    const float* __restrict__ g5, const float* __restrict__ be5,
    const float* __restrict__ wt6, const float* __restrict__ b6,
    const float* __restrict__ g6, const float* __restrict__ be6,
    float* __restrict__ featT) {

    __shared__ __align__(16) float s_pad32[34 * 34];
    __shared__ __align__(16) float s_pad16[18 * 18];
    __shared__ __align__(16) float s_act[32 * 32];
    __shared__ float s_red[64];

    const int b   = blockIdx.x;
    const int tid = threadIdx.x;
    const float* ab = act3 + (size_t)b * 4096;

    for (int p = tid; p < 34 * 34; p += NTB) s_pad32[p] = 0.f;
    for (int p = tid; p < 18 * 18; p += NTB) s_pad16[p] = 0.f;
    __syncthreads();

    // ---- norm3 + pool -> s_pad32 ----
    {
        const float mean = accS3[b] * (1.0f / 4096.0f);
        const float rstd = rsqrtf(accQ3[b] * (1.0f / 4096.0f) - mean * mean + 1e-5f);
        if (tid < 32 * 32) {
            const int oi = tid >> 5, oj = tid & 31;
            float m = -INFINITY;
#pragma unroll
            for (int di = 0; di < 2; di++)
#pragma unroll
                for (int dj = 0; dj < 2; dj++) {
                    const int idx = (2 * oi + di) * 64 + (2 * oj + dj);
                    float v = (ab[idx] - mean) * rstd * g3[idx] + be3[idx];
                    m = fmaxf(m, v);
                }
            s_pad32[(oi + 1) * 34 + (oj + 1)] = m;
        }
        __syncthreads();
    }

    float mean, rstd;

    // ---- L4 ----
    lc_small<32, 34>(wt4, b4, s_pad32, s_act, mean, rstd, s_red);
    if (tid < 32 * 32) {
        const int i = tid >> 5, j = tid & 31;
        s_pad32[(i + 1) * 34 + (j + 1)] =
            (s_act[tid] - mean) * rstd * g4[tid] + be4[tid];
    }
    __syncthreads();

    // ---- L5 + pool ----
    lc_small<32, 34>(wt5, b5, s_pad32, s_act, mean, rstd, s_red);
    if (tid < 16 * 16) {
        const int oi = tid >> 4, oj = tid & 15;
        float m = -INFINITY;
#pragma unroll
        for (int di = 0; di < 2; di++)
#pragma unroll
            for (int dj = 0; dj < 2; dj++) {
                const int idx = (2 * oi + di) * 32 + (2 * oj + dj);
                float v = (s_act[idx] - mean) * rstd * g5[idx] + be5[idx];
                m = fmaxf(m, v);
            }
        s_pad16[(oi + 1) * 18 + (oj + 1)] = m;
    }
    __syncthreads();

    // ---- L6 -> featT ----
    lc_small<16, 18>(wt6, b6, s_pad16, s_act, mean, rstd, s_red);
    if (tid < 256) {
        float v = (s_act[tid] - mean) * rstd * g6[tid] + be6[tid];
        featT[(size_t)tid * 64 + b] = v;
    }
}

// ===========================================================================
// FC GEMM: 256 blocks x 4 outputs x 64 images.  Weights read once chip-wide.
// ===========================================================================
__global__ __launch_bounds__(256) void fc_gemm(const float4* __restrict__ featT4,
                                               const float* __restrict__ fcw,
                                               const float* __restrict__ fcb,
                                               float* __restrict__ logits) {
    __shared__ float sw[4 * 256];
    __shared__ __align__(16) float sf[128 * 64];
    const int tid = threadIdx.x;
    const int o0  = blockIdx.x * 4;
    const int o_l = tid >> 6;
    const int img = tid & 63;

    for (int idx = tid; idx < 1024; idx += 256)
        sw[idx] = fcw[(size_t)o0 * 256 + idx];

    float acc = fcb[o0 + o_l];
#pragma unroll
    for (int k0 = 0; k0 < 256; k0 += 128) {
        __syncthreads();
        float4* sf4 = (float4*)sf;
        for (int idx = tid; idx < 128 * 16; idx += 256)
            sf4[idx] = featT4[(size_t)k0 * 16 + idx];
        __syncthreads();
#pragma unroll 8
        for (int k = 0; k < 128; k++)
            acc = fmaf(sw[o_l * 256 + k0 + k], sf[k * 64 + img], acc);
    }
    logits[(size_t)img * 1024 + o0 + o_l] = acc;
}

// ===========================================================================
// Softmax over 1024, one block per image.
// ===========================================================================
__global__ __launch_bounds__(256) void softmax_kernel(const float4* __restrict__ logits4,
                                                      float4* __restrict__ out4) {
    __shared__ float red[8];
    const int b = blockIdx.x, tid = threadIdx.x;
    const int wid = tid >> 5, lane = tid & 31;

    float4 l = logits4[(size_t)b * 256 + tid];
    float m = fmaxf(fmaxf(l.x, l.y), fmaxf(l.z, l.w));
#pragma unroll
    for (int o = 16; o > 0; o >>= 1)
        m = fmaxf(m, __shfl_xor_sync(0xffffffffu, m, o));
    if (lane == 0) red[wid] = m;
    __syncthreads();
    float M = red[0];
#pragma unroll
    for (int w = 1; w < 8; w++) M = fmaxf(M, red[w]);
    __syncthreads();

    float4 e = make_float4(__expf(l.x - M), __expf(l.y - M),
                           __expf(l.z - M), __expf(l.w - M));
    float s = e.x + e.y + e.z + e.w;
#pragma unroll
    for (int o = 16; o > 0; o >>= 1)
        s += __shfl_xor_sync(0xffffffffu, s, o);
    if (lane == 0) red[wid] = s;
    __syncthreads();
    float S = 0.f;
#pragma unroll
    for (int w = 0; w < 8; w++) S += red[w];
    const float R = 1.0f / S;

    out4[(size_t)b * 256 + tid] = make_float4(e.x * R, e.y * R, e.z * R, e.w * R);
}

// ===========================================================================
// Launch
// ===========================================================================
extern "C" void kernel_launch(void* const* d_in, const int* in_sizes, int n_in,
                              void* d_out, int out_size) {
    (void)in_sizes; (void)n_in; (void)out_size;

    const float* x   = (const float*)d_in[0];
    const float* w1  = (const float*)d_in[1];
    const float* b1  = (const float*)d_in[2];
    const float* g1  = (const float*)d_in[3];
    const float* be1 = (const float*)d_in[4];
    const float* w2  = (const float*)d_in[5];
    const float* b2  = (const float*)d_in[6];
    const float* g2  = (const float*)d_in[7];
    const float* be2 = (const float*)d_in[8];
    const float* w3  = (const float*)d_in[9];
    const float* b3  = (const float*)d_in[10];
    const float* g3  = (const float*)d_in[11];
    const float* be3 = (const float*)d_in[12];
    const float* w4  = (const float*)d_in[13];
    const float* b4  = (const float*)d_in[14];
    const float* g4  = (const float*)d_in[15];
    const float* be4 = (const float*)d_in[16];
    const float* w5  = (const float*)d_in[17];
    const float* b5  = (const float*)d_in[18];
    const float* g5  = (const float*)d_in[19];
    const float* be5 = (const float*)d_in[20];
    const float* w6  = (const float*)d_in[21];
    const float* b6  = (const float*)d_in[22];
    const float* g6  = (const float*)d_in[23];
    const float* be6 = (const float*)d_in[24];
    const float* fcw = (const float*)d_in[25];
    const float* fcb = (const float*)d_in[26];
    float* out = (float*)d_out;

    float *A, *B, *C, *t1, *t2, *t3, *t4, *t5, *t6, *ft, *lg, *acc;
    cudaGetSymbolAddress((void**)&A,   g_bufA);
    cudaGetSymbolAddress((void**)&B,   g_bufB);
    cudaGetSymbolAddress((void**)&C,   g_bufC);
    cudaGetSymbolAddress((void**)&t1,  g_wt1);
    cudaGetSymbolAddress((void**)&t2,  g_wt2);
    cudaGetSymbolAddress((void**)&t3,  g_wt3);
    cudaGetSymbolAddress((void**)&t4,  g_wt4);
    cudaGetSymbolAddress((void**)&t5,  g_wt5);
    cudaGetSymbolAddress((void**)&t6,  g_wt6);
    cudaGetSymbolAddress((void**)&ft,  g_featT);
    cudaGetSymbolAddress((void**)&lg,  g_logits);
    cudaGetSymbolAddress((void**)&acc, g_acc);

    float* aS1 = acc;       float* aQ1 = acc + 64;
    float* aS2 = acc + 128; float* aQ2 = acc + 192;
    float* aS3 = acc + 256; float* aQ3 = acc + 320;

    transpose_lc<<<840, 256>>>(w1, w2, w3, w4, w5, w6,
                               t1, t2, t3, t4, t5, t6, acc);

    lc1_kernel<4, 8><<<dim3(32, 8), 512>>>(x, t1, b1, A, aS1, aQ1);

    // L2: input = norm1(pool(bufA)); 1024 blocks, one image per block
    lc64_kernel<true><<<dim3(16, 64), 256>>>(A, aS1, aQ1, g1, be1,
                                             t2, b2, B, aS2, aQ2);

    // L3: input = norm2(bufB); 1024 blocks
    lc64_kernel<false><<<dim3(16, 64), 256>>>(B, aS2, aQ2, g2, be2,
                                              t3, b3, C, aS3, aQ3);

    tail_kernel<<<64, NTB>>>(C, aS3, aQ3, g3, be3,
                             t4, b4, g4, be4, t5, b5, g5, be5,
                             t6, b6, g6, be6, ft);

    fc_gemm<<<256, 256>>>((const float4*)ft, fcw, fcb, lg);
    softmax_kernel<<<64, 256>>>((const float4*)lg, (float4*)out);
}

// round 15
// speedup vs baseline: 1.4464x; 1.0417x over previous
#include <cuda_runtime.h>
#include <cuda_bf16.h>
#include <math.h>
#include <stdint.h>

// ---------------------------------------------------------------------------
// Scratch (allocation-free device globals)
// ---------------------------------------------------------------------------
__device__ float g_bufA[64 * 128 * 128];                  // pre-norm L1 acts
__device__ float g_bufB[64 * 64 * 64];                    // pre-norm L2 acts
__device__ float g_bufC[64 * 64 * 64];                    // pre-norm L3 acts
__device__ __align__(16) float g_wt1[16384 * 49];         // [k][pix]
__device__ __align__(16) float g_wt2[4096 * 25];
__device__ __align__(16) float g_wt3[4096 * 25];
__device__ __align__(16) float g_wt4[1024 * 9];
__device__ __align__(16) float g_wt5[1024 * 9];
__device__ __align__(16) float g_wt6[256 * 9];
__device__ __align__(16) float g_featT[256 * 64];         // [k][img]
__device__ __align__(16) float g_logits[64 * 1024];
__device__ float g_acc[6 * 64];                           // S1,Q1,S2,Q2,S3,Q3

// ---------------------------------------------------------------------------
// cp.async helpers
// ---------------------------------------------------------------------------
__device__ __forceinline__ void cp_async4(unsigned int dst, const void* src) {
    asm volatile("cp.async.ca.shared.global [%0], [%1], 4;" :: "r"(dst), "l"(src));
}
__device__ __forceinline__ void cp_async16(unsigned int dst, const void* src) {
    asm volatile("cp.async.cg.shared.global [%0], [%1], 16;" :: "r"(dst), "l"(src));
}
__device__ __forceinline__ void cp_commit() {
    asm volatile("cp.async.commit_group;");
}
template <int N>
__device__ __forceinline__ void cp_wait() {
    asm volatile("cp.async.wait_group %0;" :: "n"(N));
}

// ===========================================================================
// Weight transpose (coalesced both sides) + zero the stat accumulators.
// ===========================================================================
__global__ __launch_bounds__(256) void transpose_lc(
    const float* __restrict__ w1, const float* __restrict__ w2,
    const float* __restrict__ w3, const float* __restrict__ w4,
    const float* __restrict__ w5, const float* __restrict__ w6,
    float* __restrict__ t1, float* __restrict__ t2, float* __restrict__ t3,
    float* __restrict__ t4, float* __restrict__ t5, float* __restrict__ t6,
    float* __restrict__ acc) {
    if (blockIdx.x == 0)
        for (int i = threadIdx.x; i < 6 * 64; i += 256) acc[i] = 0.f;
    __shared__ float s[32 * 49];
    int tile = blockIdx.x;
    const float* in; float* out; int N, K;
    if      (tile < 512) {             in = w1; out = t1; N = 16384; K = 49; }
    else if (tile < 640) { tile -= 512; in = w2; out = t2; N = 4096;  K = 25; }
    else if (tile < 768) { tile -= 640; in = w3; out = t3; N = 4096;  K = 25; }
    else if (tile < 800) { tile -= 768; in = w4; out = t4; N = 1024;  K = 9;  }
    else if (tile < 832) { tile -= 800; in = w5; out = t5; N = 1024;  K = 9;  }
    else                 { tile -= 832; in = w6; out = t6; N = 256;   K = 9;  }
    const int p0  = tile * 32;
    const int tot = 32 * K;
    const int tid = threadIdx.x;
    for (int idx = tid; idx < tot; idx += 256) s[idx] = in[(size_t)p0 * K + idx];
    __syncthreads();
    for (int idx = tid; idx < tot; idx += 256) {
        int k = idx >> 5, pl = idx & 31;
        out[(size_t)k * N + p0 + pl] = s[pl * K + k];
    }
}

// ===========================================================================
// L1: LC 7x7 on 128x128 + ReLU + stat atomics.
// cp.async double-buffered over the BCH-image loop: stage(i+1) overlaps
// compute(i).  OOB halo entries zeroed once and never rewritten.
// ===========================================================================
template <int RPB, int BCH>
__global__ __launch_bounds__(512) void lc1_kernel(const float* __restrict__ in,
                                                  const float* __restrict__ wt,
                                                  const float* __restrict__ bias,
                                                  float* __restrict__ act,
                                                  float* __restrict__ accS,
                                                  float* __restrict__ accQ) {
    constexpr int H = 128, W = 128, K = 7, PAD = 3, KK = 49, N = H * W;
    constexpr int IW = W + 2 * PAD;      // 134
    constexpr int IR = RPB + 2 * PAD;    // 10
    constexpr int NT = RPB * W;          // 512
    constexpr int TILE = IR * IW;        // 1340

    __shared__ float sbuf[2][TILE];
    __shared__ float sred[32];

    const int r0  = blockIdx.x * RPB;
    const int b0  = blockIdx.y * BCH;
    const int tid = threadIdx.x;
    const int li  = tid / W;
    const int lj  = tid % W;
    const int pix = (r0 + li) * W + lj;

    float wr[KK];
#pragma unroll
    for (int t = 0; t < KK; t++) wr[t] = wt[(size_t)t * N + pix];
    const float bb = bias[pix];

    // zero both buffers (OOB entries stay zero for the whole kernel)
    for (int idx = tid; idx < 2 * TILE; idx += NT) ((float*)sbuf)[idx] = 0.f;
    __syncthreads();

    const unsigned int sb0 = (unsigned int)__cvta_generic_to_shared(&sbuf[0][0]);
    const unsigned int sb1 = (unsigned int)__cvta_generic_to_shared(&sbuf[1][0]);

    // stage image bi into buffer buf (in-bounds elements only)
    auto stage = [&](int bi, int buf) {
        const float* inb = in + (size_t)(b0 + bi) * N;
        const unsigned int sb = buf ? sb1 : sb0;
        for (int idx = tid; idx < TILE; idx += NT) {
            const int r = idx / IW, c = idx % IW;
            const int gi = r0 - PAD + r, gj = c - PAD;
            if (gi >= 0 && gi < H && gj >= 0 && gj < W)
                cp_async4(sb + idx * 4, inb + gi * W + gj);
        }
        cp_commit();
    };

    stage(0, 0);

    for (int bi = 0; bi < BCH; bi++) {
        if (bi < BCH - 1) { stage(bi + 1, (bi + 1) & 1); cp_wait<1>(); }
        else              { cp_wait<0>(); }
        __syncthreads();

        const float* cur = sbuf[bi & 1];
        float sum = bb;
#pragma unroll
        for (int kh = 0; kh < K; kh++)
#pragma unroll
            for (int kw = 0; kw < K; kw++)
                sum = fmaf(wr[kh * K + kw], cur[(li + kh) * IW + (lj + kw)], sum);

        const int b = b0 + bi;
        float v = fmaxf(sum, 0.f);
        act[(size_t)b * N + pix] = v;

        float s = v, q = v * v;
#pragma unroll
        for (int o = 16; o > 0; o >>= 1) {
            s += __shfl_down_sync(0xffffffffu, s, o);
            q += __shfl_down_sync(0xffffffffu, q, o);
        }
        const int wid = tid >> 5;
        if ((tid & 31) == 0) { sred[wid] = s; sred[16 + wid] = q; }
        __syncthreads();   // also orders compute(bi) reads before stage(bi+2) writes
        if (tid == 0) {
            float ts = 0.f, tq = 0.f;
#pragma unroll
            for (int k = 0; k < 16; k++) { ts += sred[k]; tq += sred[16 + k]; }
            atomicAdd(&accS[b], ts);
            atomicAdd(&accQ[b], tq);
        }
    }
}

// ===========================================================================
// L2 / L3: LC 5x5 on 64x64, one block = (4 rows x 64 cols, ONE image).
// Block weight slab (25.6 KB) streamed into smem via cp.async (no register
// pressure), overlapped with the normalized input staging.
// ===========================================================================
template <bool POOLIN>
__global__ __launch_bounds__(256) void lc64_kernel(
    const float* __restrict__ prevAct,
    const float* __restrict__ accSp, const float* __restrict__ accQp,
    const float* __restrict__ gp, const float* __restrict__ bep,
    const float* __restrict__ wt, const float* __restrict__ bias,
    float* __restrict__ act,
    float* __restrict__ accSo, float* __restrict__ accQo) {
    constexpr int H = 64, K = 5, PAD = 2, KK = 25, N = H * H;
    constexpr int RPB = 4, NT = 256;
    constexpr int IW = H + 2 * PAD;      // 68
    constexpr int IR = RPB + 2 * PAD;    // 8
    constexpr float INV_PREV = POOLIN ? (1.0f / 16384.0f) : (1.0f / 4096.0f);

    __shared__ __align__(16) float sw[KK * 256];   // [k][px_local]
    __shared__ float sin[IR * IW];
    __shared__ float sred[16];

    const int r0  = blockIdx.x * RPB;
    const int b   = blockIdx.y;
    const int tid = threadIdx.x;
    const int li  = tid >> 6;
    const int lj  = tid & 63;
    const int pix = (r0 + li) * H + lj;
    const int px0 = blockIdx.x * 256;

    // ---- weights -> smem via cp.async (1600 float4s, 7 per thread) --------
    {
        const unsigned int swa = (unsigned int)__cvta_generic_to_shared(sw);
#pragma unroll
        for (int i = 0; i < 7; i++) {
            const int idx = tid + i * 256;            // float4 index
            if (idx < KK * 64) {
                const int k = idx >> 6, e = idx & 63;
                cp_async16(swa + (k * 256 + e * 4) * 4,
                           wt + (size_t)k * N + px0 + e * 4);
            }
        }
        cp_commit();
    }

    // ---- stage normalized(+pooled) input tile (overlaps the cp.asyncs) ----
    const float mean = accSp[b] * INV_PREV;
    const float rstd = rsqrtf(accQp[b] * INV_PREV - mean * mean + 1e-5f);

    for (int idx = tid; idx < IR * IW; idx += NT) {
        const int r = idx / IW, c = idx % IW;
        const int oi = r0 - PAD + r, oj = c - PAD;
        float v = 0.f;
        if (oi >= 0 && oi < H && oj >= 0 && oj < H) {
            if (POOLIN) {
                const float* ab = prevAct + (size_t)b * 16384;
                float m = -INFINITY;
#pragma unroll
                for (int di = 0; di < 2; di++)
#pragma unroll
                    for (int dj = 0; dj < 2; dj++) {
                        const int idx1 = (2 * oi + di) * 128 + (2 * oj + dj);
                        float t = (ab[idx1] - mean) * rstd * gp[idx1] + bep[idx1];
                        m = fmaxf(m, t);
                    }
                v = m;
            } else {
                const int idx1 = oi * H + oj;
                v = (prevAct[(size_t)b * N + idx1] - mean) * rstd * gp[idx1] + bep[idx1];
            }
        }
        sin[idx] = v;
    }

    const float bb = bias[pix];
    cp_wait<0>();
    __syncthreads();

    float sum = bb;
#pragma unroll
    for (int kh = 0; kh < K; kh++)
#pragma unroll
        for (int kw = 0; kw < K; kw++)
            sum = fmaf(sw[(kh * K + kw) * 256 + tid],
                       sin[(li + kh) * IW + (lj + kw)], sum);

    float v = fmaxf(sum, 0.f);
    act[(size_t)b * N + pix] = v;

    float s = v, q = v * v;
#pragma unroll
    for (int o = 16; o > 0; o >>= 1) {
        s += __shfl_down_sync(0xffffffffu, s, o);
        q += __shfl_down_sync(0xffffffffu, q, o);
    }
    const int wid = tid >> 5;
    if ((tid & 31) == 0) { sred[wid] = s; sred[8 + wid] = q; }
    __syncthreads();
    if (tid == 0) {
        float ts = 0.f, tq = 0.f;
#pragma unroll
        for (int k = 0; k < 8; k++) { ts += sred[k]; tq += sred[8 + k]; }
        atomicAdd(&accSo[b], ts);
        atomicAdd(&accQo[b], tq);
    }
}

// ===========================================================================
// Tail: norm3+pool, L4, L5, L6 -> featT.  One block per image, 1024 threads.
// ===========================================================================
#define NTB 1024

__device__ __forceinline__ void block_sum2(float& s, float& q, float* red) {
#pragma unroll
    for (int o = 16; o > 0; o >>= 1) {
        s += __shfl_down_sync(0xffffffffu, s, o);
        q += __shfl_down_sync(0xffffffffu, q, o);
    }
    const int wid = threadIdx.x >> 5, lane = threadIdx.x & 31;
    if (lane == 0) { red[wid] = s; red[32 + wid] = q; }
    __syncthreads();
    if (wid == 0) {
        s = red[lane]; q = red[32 + lane];
#pragma unroll
        for (int o = 16; o > 0; o >>= 1) {
            s += __shfl_down_sync(0xffffffffu, s, o);
            q += __shfl_down_sync(0xffffffffu, q, o);
        }
        if (lane == 0) { red[0] = s; red[32] = q; }
    }
    __syncthreads();
    s = red[0]; q = red[32];
}

template <int H, int PWIDTH>
__device__ __forceinline__ void lc_small(const float* __restrict__ wt,
                                         const float* __restrict__ bias,
                                         const float* s_in, float* s_act,
                                         float& mean, float& rstd, float* red) {
    constexpr int N = H * H;
    const int tid = threadIdx.x;
    float s = 0.f, q = 0.f;
    if (tid < N) {
        const int i = tid / H, j = tid % H;
        const float* sp0 = s_in + i * PWIDTH + j;
        float acc = bias[tid];
#pragma unroll
        for (int kh = 0; kh < 3; kh++)
#pragma unroll
            for (int kw = 0; kw < 3; kw++)
                acc = fmaf(wt[(size_t)(kh * 3 + kw) * N + tid],
                           sp0[kh * PWIDTH + kw], acc);
        float v = fmaxf(acc, 0.f);
        s_act[tid] = v;
        s = v; q = v * v;
    }
    block_sum2(s, q, red);
    mean = s * (1.0f / N);
    rstd = rsqrtf(q * (1.0f / N) - mean * mean + 1e-5f);
}

__global__ __launch_bounds__(NTB) void tail_kernel(
    const float* __restrict__ act3,
    const float* __restrict__ accS3, const float* __restrict__ accQ3,
    const float* __restrict__ g3, const float* __restrict__ be3,
    const float* __restrict__ wt4, const float* __restrict__ b4,
    const float* __restrict__ g4, const float* __restrict__ be4,
    const float* __restrict__ wt5, const float* __restrict__ b5,
    const float* __restrict__ g5, const float* __restrict__ be5,
    const float* __restrict__ wt6, const float* __restrict__ b6,
    const float* __restrict__ g6, const float* __restrict__ be6,
    float* __restrict__ featT) {

    __shared__ __align__(16) float s_pad32[34 * 34];
    __shared__ __align__(16) float s_pad16[18 * 18];
    __shared__ __align__(16) float s_act[32 * 32];
    __shared__ float s_red[64];

    const int b   = blockIdx.x;
    const int tid = threadIdx.x;
    const float* ab = act3 + (size_t)b * 4096;

    for (int p = tid; p < 34 * 34; p += NTB) s_pad32[p] = 0.f;
    for (int p = tid; p < 18 * 18; p += NTB) s_pad16[p] = 0.f;
    __syncthreads();

    // ---- norm3 + pool -> s_pad32 ----
    {
        const float mean = accS3[b] * (1.0f / 4096.0f);
        const float rstd = rsqrtf(accQ3[b] * (1.0f / 4096.0f) - mean * mean + 1e-5f);
        if (tid < 32 * 32) {
            const int oi = tid >> 5, oj = tid & 31;
            float m = -INFINITY;
#pragma unroll
            for (int di = 0; di < 2; di++)
#pragma unroll
                for (int dj = 0; dj < 2; dj++) {
                    const int idx = (2 * oi + di) * 64 + (2 * oj + dj);
                    float v = (ab[idx] - mean) * rstd * g3[idx] + be3[idx];
                    m = fmaxf(m, v);
                }
            s_pad32[(oi + 1) * 34 + (oj + 1)] = m;
        }
        __syncthreads();
    }

    float mean, rstd;

    lc_small<32, 34>(wt4, b4, s_pad32, s_act, mean, rstd, s_red);
    if (tid < 32 * 32) {
        const int i = tid >> 5, j = tid & 31;
        s_pad32[(i + 1) * 34 + (j + 1)] =
            (s_act[tid] - mean) * rstd * g4[tid] + be4[tid];
    }
    __syncthreads();

    lc_small<32, 34>(wt5, b5, s_pad32, s_act, mean, rstd, s_red);
    if (tid < 16 * 16) {
        const int oi = tid >> 4, oj = tid & 15;
        float m = -INFINITY;
#pragma unroll
        for (int di = 0; di < 2; di++)
#pragma unroll
            for (int dj = 0; dj < 2; dj++) {
                const int idx = (2 * oi + di) * 32 + (2 * oj + dj);
                float v = (s_act[idx] - mean) * rstd * g5[idx] + be5[idx];
                m = fmaxf(m, v);
            }
        s_pad16[(oi + 1) * 18 + (oj + 1)] = m;
    }
    __syncthreads();

    lc_small<16, 18>(wt6, b6, s_pad16, s_act, mean, rstd, s_red);
    if (tid < 256) {
        float v = (s_act[tid] - mean) * rstd * g6[tid] + be6[tid];
        featT[(size_t)tid * 64 + b] = v;
    }
}

// ===========================================================================
// FC GEMM: 256 blocks x 4 outputs x 64 images.  Weights read once chip-wide.
// ===========================================================================
__global__ __launch_bounds__(256) void fc_gemm(const float4* __restrict__ featT4,
                                               const float* __restrict__ fcw,
                                               const float* __restrict__ fcb,
                                               float* __restrict__ logits) {
    __shared__ float sw[4 * 256];
    __shared__ __align__(16) float sf[128 * 64];
    const int tid = threadIdx.x;
    const int o0  = blockIdx.x * 4;
    const int o_l = tid >> 6;
    const int img = tid & 63;

    for (int idx = tid; idx < 1024; idx += 256)
        sw[idx] = fcw[(size_t)o0 * 256 + idx];

    float acc = fcb[o0 + o_l];
#pragma unroll
    for (int k0 = 0; k0 < 256; k0 += 128) {
        __syncthreads();
        float4* sf4 = (float4*)sf;
        for (int idx = tid; idx < 128 * 16; idx += 256)
            sf4[idx] = featT4[(size_t)k0 * 16 + idx];
        __syncthreads();
#pragma unroll 8
        for (int k = 0; k < 128; k++)
            acc = fmaf(sw[o_l * 256 + k0 + k], sf[k * 64 + img], acc);
    }
    logits[(size_t)img * 1024 + o0 + o_l] = acc;
}

// ===========================================================================
// Softmax over 1024, one block per image.
// ===========================================================================
__global__ __launch_bounds__(256) void softmax_kernel(const float4* __restrict__ logits4,
                                                      float4* __restrict__ out4) {
    __shared__ float red[8];
    const int b = blockIdx.x, tid = threadIdx.x;
    const int wid = tid >> 5, lane = tid & 31;

    float4 l = logits4[(size_t)b * 256 + tid];
    float m = fmaxf(fmaxf(l.x, l.y), fmaxf(l.z, l.w));
#pragma unroll
    for (int o = 16; o > 0; o >>= 1)
        m = fmaxf(m, __shfl_xor_sync(0xffffffffu, m, o));
    if (lane == 0) red[wid] = m;
    __syncthreads();
    float M = red[0];
#pragma unroll
    for (int w = 1; w < 8; w++) M = fmaxf(M, red[w]);
    __syncthreads();

    float4 e = make_float4(__expf(l.x - M), __expf(l.y - M),
                           __expf(l.z - M), __expf(l.w - M));
    float s = e.x + e.y + e.z + e.w;
#pragma unroll
    for (int o = 16; o > 0; o >>= 1)
        s += __shfl_xor_sync(0xffffffffu, s, o);
    if (lane == 0) red[wid] = s;
    __syncthreads();
    float S = 0.f;
#pragma unroll
    for (int w = 0; w < 8; w++) S += red[w];
    const float R = 1.0f / S;

    out4[(size_t)b * 256 + tid] = make_float4(e.x * R, e.y * R, e.z * R, e.w * R);
}

// ===========================================================================
// Launch
// ===========================================================================
extern "C" void kernel_launch(void* const* d_in, const int* in_sizes, int n_in,
                              void* d_out, int out_size) {
    (void)in_sizes; (void)n_in; (void)out_size;

    const float* x   = (const float*)d_in[0];
    const float* w1  = (const float*)d_in[1];
    const float* b1  = (const float*)d_in[2];
    const float* g1  = (const float*)d_in[3];
    const float* be1 = (const float*)d_in[4];
    const float* w2  = (const float*)d_in[5];
    const float* b2  = (const float*)d_in[6];
    const float* g2  = (const float*)d_in[7];
    const float* be2 = (const float*)d_in[8];
    const float* w3  = (const float*)d_in[9];
    const float* b3  = (const float*)d_in[10];
    const float* g3  = (const float*)d_in[11];
    const float* be3 = (const float*)d_in[12];
    const float* w4  = (const float*)d_in[13];
    const float* b4  = (const float*)d_in[14];
    const float* g4  = (const float*)d_in[15];
    const float* be4 = (const float*)d_in[16];
    const float* w5  = (const float*)d_in[17];
    const float* b5  = (const float*)d_in[18];
    const float* g5  = (const float*)d_in[19];
    const float* be5 = (const float*)d_in[20];
    const float* w6  = (const float*)d_in[21];
    const float* b6  = (const float*)d_in[22];
    const float* g6  = (const float*)d_in[23];
    const float* be6 = (const float*)d_in[24];
    const float* fcw = (const float*)d_in[25];
    const float* fcb = (const float*)d_in[26];
    float* out = (float*)d_out;

    float *A, *B, *C, *t1, *t2, *t3, *t4, *t5, *t6, *ft, *lg, *acc;
    cudaGetSymbolAddress((void**)&A,   g_bufA);
    cudaGetSymbolAddress((void**)&B,   g_bufB);
    cudaGetSymbolAddress((void**)&C,   g_bufC);
    cudaGetSymbolAddress((void**)&t1,  g_wt1);
    cudaGetSymbolAddress((void**)&t2,  g_wt2);
    cudaGetSymbolAddress((void**)&t3,  g_wt3);
    cudaGetSymbolAddress((void**)&t4,  g_wt4);
    cudaGetSymbolAddress((void**)&t5,  g_wt5);
    cudaGetSymbolAddress((void**)&t6,  g_wt6);
    cudaGetSymbolAddress((void**)&ft,  g_featT);
    cudaGetSymbolAddress((void**)&lg,  g_logits);
    cudaGetSymbolAddress((void**)&acc, g_acc);

    float* aS1 = acc;       float* aQ1 = acc + 64;
    float* aS2 = acc + 128; float* aQ2 = acc + 192;
    float* aS3 = acc + 256; float* aQ3 = acc + 320;

    transpose_lc<<<840, 256>>>(w1, w2, w3, w4, w5, w6,
                               t1, t2, t3, t4, t5, t6, acc);

    lc1_kernel<4, 8><<<dim3(32, 8), 512>>>(x, t1, b1, A, aS1, aQ1);

    lc64_kernel<true><<<dim3(16, 64), 256>>>(A, aS1, aQ1, g1, be1,
                                             t2, b2, B, aS2, aQ2);

    lc64_kernel<false><<<dim3(16, 64), 256>>>(B, aS2, aQ2, g2, be2,
                                              t3, b3, C, aS3, aQ3);

    tail_kernel<<<64, NTB>>>(C, aS3, aQ3, g3, be3,
                             t4, b4, g4, be4, t5, b5, g5, be5,
                             t6, b6, g6, be6, ft);

    fc_gemm<<<256, 256>>>((const float4*)ft, fcw, fcb, lg);
    softmax_kernel<<<64, 256>>>((const float4*)lg, (float4*)out);
}